// round 1
// baseline (speedup 1.0000x reference)
#include <cuda_runtime.h>
#include <math.h>

#define NN 10000
#define EE 100000
#define CC 16
#define HH 4
#define SS 4
#define BB 16
#define HIDN 64
#define TP_NORM 0.125f       // 1/sqrt(C*S)
#define LOGIT_SCALE 0.125f   // DOT_NORM * SCALE = (1/4)*(1/2)
#define INV_RADIUS 0.2f      // 1/5.0

// ---------------- scratch (device globals: allowed scratch mechanism) -------
__device__ float g_Qk[NN * 4096];   // [n][hid*64 + s*16 + k]
__device__ float g_Qv[NN * 4096];
__device__ float g_QbK[NN * 64];    // bias part: [n][s*16+k]
__device__ float g_QbV[NN * 64];
__device__ float g_q[NN * CC];
__device__ int   g_deg[NN];
__device__ int   g_rowptr[NN + 1];
__device__ int   g_cursor[NN];
__device__ int   g_eorder[EE];
__device__ float g_den[NN * HH];
__device__ float g_agg[NN * CC];

__device__ __forceinline__ float sigmoidf_(float x) { return 1.0f / (1.0f + expf(-x)); }

// ---------------- K0: init accumulators -------------------------------------
__global__ void k_init() {
    int i = blockIdx.x * 256 + threadIdx.x;
    if (i < NN * CC) g_agg[i] = 0.0f;
    if (i < NN * HH) g_den[i] = 0.0f;
    if (i < NN)      g_deg[i] = 0;
}

// ---------------- K1: degree histogram by src --------------------------------
__global__ void k_hist(const int* __restrict__ eidx) {
    int e = blockIdx.x * 256 + threadIdx.x;
    if (e < EE) atomicAdd(&g_deg[eidx[e]], 1);
}

// ---------------- K2: exclusive scan (single block) --------------------------
__global__ void k_scan() {
    __shared__ int ps[1024];
    const int PER = 10;                    // 1024*10 = 10240 >= NN
    int t = threadIdx.x;
    int start = t * PER;
    int sum = 0;
    for (int i = 0; i < PER; i++) {
        int idx = start + i;
        if (idx < NN) sum += g_deg[idx];
    }
    ps[t] = sum;
    __syncthreads();
    for (int off = 1; off < 1024; off <<= 1) {
        int add = (t >= off) ? ps[t - off] : 0;
        __syncthreads();
        ps[t] += add;
        __syncthreads();
    }
    int base = ps[t] - sum;                // exclusive prefix
    for (int i = 0; i < PER; i++) {
        int idx = start + i;
        if (idx < NN) {
            g_rowptr[idx] = base;
            g_cursor[idx] = base;
            base += g_deg[idx];
        }
    }
    if (t == 1023) g_rowptr[NN] = ps[1023];
}

// ---------------- K3: scatter edge ids grouped by src ------------------------
__global__ void k_scatter(const int* __restrict__ eidx) {
    int e = blockIdx.x * 256 + threadIdx.x;
    if (e < EE) {
        int s = eidx[e];
        int pos = atomicAdd(&g_cursor[s], 1);
        g_eorder[pos] = e;
    }
}

// ---------------- K4: q = X @ Wq ---------------------------------------------
__global__ void k_qproj(const float* __restrict__ xf, const float* __restrict__ Wq) {
    __shared__ float Ws[256];
    int t = threadIdx.x;
    if (t < 256) Ws[t] = Wq[t];
    __syncthreads();
    int idx = blockIdx.x * 256 + t;
    if (idx >= NN * CC) return;
    int n = idx >> 4, k = idx & 15;
    float s = 0.0f;
#pragma unroll
    for (int c = 0; c < 16; c++) s += xf[n * 16 + c] * Ws[c * 16 + k];
    g_q[idx] = s;
}

// ---------------- K5: per-node Q tensors: Q[n,hid,s,k] = sum_c x*W2 ----------
// grid: (ceil(N/64), 65, 2). y==64 computes the bias part Qb from b2.
__global__ void k_qweights(const float* __restrict__ xf,
                           const float* __restrict__ kW2, const float* __restrict__ kb2,
                           const float* __restrict__ vW2, const float* __restrict__ vb2) {
    int n0 = blockIdx.x * 64;
    int hid = blockIdx.y;                  // 0..64
    int tz = blockIdx.z;
    const float* W2 = tz ? vW2 : kW2;
    const float* b2 = tz ? vb2 : kb2;
    float* Q  = tz ? g_Qv  : g_Qk;
    float* Qb = tz ? g_QbV : g_QbK;

    __shared__ float Xs[64 * 16];
    __shared__ float Ws[16 * 64];
    int t = threadIdx.x;
    for (int i = t; i < 64 * 16; i += 256) {
        int n = n0 + (i >> 4);
        Xs[i] = (n < NN) ? xf[n * 16 + (i & 15)] : 0.0f;
    }
    const float* wsrc = (hid < 64) ? (W2 + hid * 1024) : b2;   // layout c*64 + s*16 + k
    for (int i = t; i < 1024; i += 256) Ws[i] = wsrc[i];
    __syncthreads();

#pragma unroll
    for (int i = 0; i < 16; i++) {
        int o = i * 256 + t;
        int nl = o >> 6, j2 = o & 63;
        float acc = 0.0f;
#pragma unroll
        for (int c = 0; c < 16; c++) acc += Xs[nl * 16 + c] * Ws[c * 64 + j2];
        int n = n0 + nl;
        if (n < NN) {
            if (hid < 64) Q[(size_t)n * 4096 + hid * 64 + j2] = acc;
            else          Qb[n * 64 + j2] = acc;
        }
    }
}

// ---------------- K6: main edge kernel (one block per source node) -----------
__global__ void __launch_bounds__(128) k_edges(
    const float* __restrict__ sh, const float* __restrict__ emb,
    const float* __restrict__ elen,
    const float* __restrict__ kW1, const float* __restrict__ kb1,
    const float* __restrict__ vW1, const float* __restrict__ vb1,
    const float* __restrict__ Wdot, const int* __restrict__ eidx) {

    __shared__ float Qk[4096], Qv[4096];
    __shared__ float QbK[64], QbV[64];
    __shared__ float W1k[1024], W1v[1024], b1k[64], b1v[64];
    __shared__ float Wd[16];
    __shared__ float emb_s[8][16];
    __shared__ float sh_s[8][4];
    __shared__ float h1k[8][64], h1v[8][64];
    __shared__ int   dst_s[8];
    __shared__ int   eid_s[8];
    __shared__ float cut_s[8];

    int node = blockIdx.x;
    int t = threadIdx.x;
    int r0 = g_rowptr[node], r1 = g_rowptr[node + 1];
    int deg = r1 - r0;
    if (deg == 0) return;

    for (int i = t; i < 1024; i += 128) { W1k[i] = kW1[i]; W1v[i] = vW1[i]; }
    for (int i = t; i < 64;   i += 128) { b1k[i] = kb1[i]; b1v[i] = vb1[i]; }
    if (t < 16) Wd[t] = Wdot[t];
    const float* qkrow = g_Qk + (size_t)node * 4096;
    const float* qvrow = g_Qv + (size_t)node * 4096;
    for (int i = t; i < 4096; i += 128) { Qk[i] = qkrow[i]; Qv[i] = qvrow[i]; }
    for (int i = t; i < 64;   i += 128) { QbK[i] = g_QbK[node * 64 + i]; QbV[i] = g_QbV[node * 64 + i]; }
    __syncthreads();

    int es = t >> 4;          // edge slot 0..7
    int k  = t & 15;          // output channel
    int head = k >> 2, j = k & 3;

    for (int base = 0; base < deg; base += 8) {
        int nloc = min(8, deg - base);
        if (t < 8) {
            if (t < nloc) {
                int e = g_eorder[r0 + base + t];
                eid_s[t] = e;
                dst_s[t] = eidx[EE + e];
                float L = elen[e];
                cut_s[t] = sigmoidf_(10.0f * (1.0f - L * INV_RADIUS));
            } else { eid_s[t] = -1; dst_s[t] = -1; cut_s[t] = 0.0f; }
        }
        __syncthreads();
        {
            int e = eid_s[es];
            emb_s[es][k] = (e >= 0) ? emb[e * 16 + k] : 0.0f;
            if (k < 4) sh_s[es][k] = (e >= 0) ? sh[e * 4 + k] : 0.0f;
        }
        __syncthreads();
        // layer-1 MLP + silu for both tensors: 8 edges x 64 hidden
        for (int i = t; i < 8 * 64; i += 128) {
            int esl = i >> 6, hid = i & 63;
            float pk = b1k[hid], pv = b1v[hid];
#pragma unroll
            for (int b = 0; b < 16; b++) {
                float em = emb_s[esl][b];
                pk += em * W1k[b * 64 + hid];
                pv += em * W1v[b * 64 + hid];
            }
            h1k[esl][hid] = pk * sigmoidf_(pk);
            h1v[esl][hid] = pv * sigmoidf_(pv);
        }
        __syncthreads();

        // contraction: k_edge/v_edge channel k of edge es
        float accK = 0.0f, accV = 0.0f;
        const float* hk = h1k[es];
        const float* hv = h1v[es];
#pragma unroll
        for (int s = 0; s < 4; s++) {
            float ik = QbK[s * 16 + k], iv = QbV[s * 16 + k];
            const float* qks = &Qk[s * 16 + k];
            const float* qvs = &Qv[s * 16 + k];
#pragma unroll 8
            for (int hid = 0; hid < 64; hid++) {
                ik += hk[hid] * qks[hid * 64];
                iv += hv[hid] * qvs[hid * 64];
            }
            float sv = sh_s[es][s];
            accK += sv * ik;
            accV += sv * iv;
        }
        float kval = accK * TP_NORM;
        float vval = accV * TP_NORM;

        // attention logit (4 lanes per head reduce over j)
        int ds = dst_s[es];
        float p = 0.0f;
        if (ds >= 0) {
            float wq = 0.0f;
#pragma unroll
            for (int i2 = 0; i2 < 4; i2++) wq += g_q[ds * 16 + head * 4 + i2] * Wd[i2 * 4 + j];
            p = kval * wq;
        }
        p += __shfl_xor_sync(0xffffffffu, p, 1);
        p += __shfl_xor_sync(0xffffffffu, p, 2);
        if (ds >= 0) {
            float logit = p * LOGIT_SCALE * cut_s[es];
            float ex = expf(logit);                 // logits are tiny; max-shift unnecessary
            if (j == 0) atomicAdd(&g_den[ds * 4 + head], ex);
            atomicAdd(&g_agg[ds * 16 + k], ex * vval);
        }
        __syncthreads();
    }
}

// ---------------- K7: finalize per node (W_out, skip, FFN) -------------------
__global__ void k_final(const float* __restrict__ xf,
                        const float* __restrict__ Wout,
                        const float* __restrict__ Wf1,
                        const float* __restrict__ Wf2,
                        float* __restrict__ out) {
    __shared__ float Wo[256], F1[512], F2[512];
    int t = threadIdx.x;
    if (t < 256) Wo[t] = Wout[t];
    for (int i = t; i < 512; i += 256) { F1[i] = Wf1[i]; F2[i] = Wf2[i]; }
    __syncthreads();
    int n = blockIdx.x * 256 + t;
    if (n >= NN) return;

    float a[16];
#pragma unroll
    for (int k = 0; k < 16; k++) {
        float d = g_den[n * 4 + (k >> 2)];
        a[k] = (d > 0.0f) ? g_agg[n * 16 + k] / d : 0.0f;
    }
    float attn[16];
#pragma unroll
    for (int k = 0; k < 16; k++) {
        float s = xf[n * 16 + k];
#pragma unroll
        for (int jj = 0; jj < 16; jj++) s += a[jj] * Wo[jj * 16 + k];
        attn[k] = s;
    }
    float na[32];
#pragma unroll
    for (int jj = 0; jj < 32; jj++) {
        float f = 0.0f;
#pragma unroll
        for (int i = 0; i < 16; i++) f += attn[i] * F1[i * 32 + jj];
        na[jj] = f * sigmoidf_(fabsf(f));
    }
#pragma unroll
    for (int k = 0; k < 16; k++) {
        float o = attn[k];
#pragma unroll
        for (int jj = 0; jj < 32; jj++) o += na[jj] * F2[jj * 16 + k];
        out[n * 16 + k] = o;
    }
}

// ---------------- launch ------------------------------------------------------
extern "C" void kernel_launch(void* const* d_in, const int* in_sizes, int n_in,
                              void* d_out, int out_size) {
    const float* xf   = (const float*)d_in[0];
    const float* sh   = (const float*)d_in[1];
    const float* emb  = (const float*)d_in[2];
    const float* elen = (const float*)d_in[3];
    const float* Wq   = (const float*)d_in[4];
    const float* kW1  = (const float*)d_in[5];
    const float* kb1  = (const float*)d_in[6];
    const float* kW2  = (const float*)d_in[7];
    const float* kb2  = (const float*)d_in[8];
    const float* vW1  = (const float*)d_in[9];
    const float* vb1  = (const float*)d_in[10];
    const float* vW2  = (const float*)d_in[11];
    const float* vb2  = (const float*)d_in[12];
    const float* Wdot = (const float*)d_in[13];
    const float* Wout = (const float*)d_in[14];
    const float* Wf1  = (const float*)d_in[15];
    const float* Wf2  = (const float*)d_in[16];
    const int*   eidx = (const int*)d_in[17];
    float* out = (float*)d_out;

    k_init<<<(NN * CC + 255) / 256, 256>>>();
    k_hist<<<(EE + 255) / 256, 256>>>(eidx);
    k_scan<<<1, 1024>>>();
    k_scatter<<<(EE + 255) / 256, 256>>>(eidx);
    k_qproj<<<(NN * CC + 255) / 256, 256>>>(xf, Wq);
    dim3 g5((NN + 63) / 64, 65, 2);
    k_qweights<<<g5, 256>>>(xf, kW2, kb2, vW2, vb2);
    k_edges<<<NN, 128>>>(sh, emb, elen, kW1, kb1, vW1, vb1, Wdot, eidx);
    k_final<<<(NN + 255) / 256, 256>>>(xf, Wout, Wf1, Wf2, out);
}

// round 2
// speedup vs baseline: 1.2333x; 1.2333x over previous
#include <cuda_runtime.h>
#include <math.h>

#define NN 10000
#define EE 100000
#define CC 16
#define HH 4
#define TP_NORM 0.125f       // 1/sqrt(C*S)
#define LOGIT_SCALE 0.125f   // DOT_NORM * SCALE
#define INV_RADIUS 0.2f

typedef unsigned long long u64;

// ---------------- scratch ----------------------------------------------------
__device__ u64   g_Qkv[(size_t)NN * 4096];   // (K,V) pairs: [n][hid*64 + s*16 + k]
__device__ u64   g_Qbkv[NN * 64];            // bias pairs:  [n][s*16 + k]
__device__ float g_qd[NN * CC];              // q @ W_dot, per node
__device__ int   g_deg[NN];
__device__ int   g_rowptr[NN + 1];
__device__ int   g_cursor[NN];
__device__ int   g_eorder[EE];
__device__ float g_den[NN * HH];
__device__ float g_agg[NN * CC];

__device__ __forceinline__ float sigmoidf_(float x) { return 1.0f / (1.0f + expf(-x)); }

__device__ __forceinline__ u64 pk2(float lo, float hi) {
    u64 r; asm("mov.b64 %0, {%1, %2};" : "=l"(r) : "f"(lo), "f"(hi)); return r;
}
__device__ __forceinline__ float2 up2(u64 v) {
    float2 f; asm("mov.b64 {%0, %1}, %2;" : "=f"(f.x), "=f"(f.y) : "l"(v)); return f;
}
__device__ __forceinline__ u64 dup2(float x) { return pk2(x, x); }
__device__ __forceinline__ u64 fma2_(u64 a, u64 b, u64 c) {
    u64 d; asm("fma.rn.f32x2 %0, %1, %2, %3;" : "=l"(d) : "l"(a), "l"(b), "l"(c)); return d;
}

// ---------------- K0: init ----------------------------------------------------
__global__ void k_init() {
    int i = blockIdx.x * 256 + threadIdx.x;
    if (i < NN * CC) g_agg[i] = 0.0f;
    if (i < NN * HH) g_den[i] = 0.0f;
    if (i < NN)      g_deg[i] = 0;
}

// ---------------- K1: degree histogram by src ---------------------------------
__global__ void k_hist(const int* __restrict__ eidx) {
    int e = blockIdx.x * 256 + threadIdx.x;
    if (e < EE) atomicAdd(&g_deg[eidx[e]], 1);
}

// ---------------- K2: exclusive scan (single block) ---------------------------
__global__ void k_scan() {
    __shared__ int ps[1024];
    const int PER = 10;
    int t = threadIdx.x;
    int start = t * PER;
    int sum = 0;
    for (int i = 0; i < PER; i++) { int idx = start + i; if (idx < NN) sum += g_deg[idx]; }
    ps[t] = sum;
    __syncthreads();
    for (int off = 1; off < 1024; off <<= 1) {
        int add = (t >= off) ? ps[t - off] : 0;
        __syncthreads();
        ps[t] += add;
        __syncthreads();
    }
    int base = ps[t] - sum;
    for (int i = 0; i < PER; i++) {
        int idx = start + i;
        if (idx < NN) { g_rowptr[idx] = base; g_cursor[idx] = base; base += g_deg[idx]; }
    }
    if (t == 1023) g_rowptr[NN] = ps[1023];
}

// ---------------- K3: scatter edges grouped by src ----------------------------
__global__ void k_scatter(const int* __restrict__ eidx) {
    int e = blockIdx.x * 256 + threadIdx.x;
    if (e < EE) {
        int s = eidx[e];
        int pos = atomicAdd(&g_cursor[s], 1);
        g_eorder[pos] = e;
    }
}

// ---------------- K4: qd[n,k] = sum_i (x@Wq)[n, h*4+i] * Wd[i*4+j] ------------
__global__ void k_qprojd(const float* __restrict__ xf, const float* __restrict__ Wq,
                         const float* __restrict__ Wdot) {
    __shared__ float Wqs[256];
    __shared__ float Wds[16];
    __shared__ float Xs[16][16];
    int t = threadIdx.x;
    if (t < 256) Wqs[t] = Wq[t];
    if (t < 16)  Wds[t] = Wdot[t];
    int n0 = blockIdx.x * 16;
    {
        int nl = t >> 4, c = t & 15;
        int n = n0 + nl;
        Xs[nl][c] = (n < NN) ? xf[n * 16 + c] : 0.0f;
    }
    __syncthreads();
    int nl = t >> 4, k = t & 15;
    int n = n0 + nl;
    if (n >= NN) return;
    int head = k >> 2, j = k & 3;
    float qd = 0.0f;
#pragma unroll
    for (int i2 = 0; i2 < 4; i2++) {
        float q = 0.0f;
#pragma unroll
        for (int c = 0; c < 16; c++) q += Xs[nl][c] * Wqs[c * 16 + head * 4 + i2];
        qd += q * Wds[i2 * 4 + j];
    }
    g_qd[n * 16 + k] = qd;
}

// ---------------- K5: per-node (K,V)-paired Q tensors -------------------------
// grid (ceil(N/64), 65); y==64 computes bias part from b2.
__global__ void k_qweights(const float* __restrict__ xf,
                           const float* __restrict__ kW2, const float* __restrict__ kb2,
                           const float* __restrict__ vW2, const float* __restrict__ vb2) {
    int n0 = blockIdx.x * 64;
    int hid = blockIdx.y;               // 0..64
    __shared__ u64 Xd[64 * 16];         // dup-packed x
    __shared__ u64 Wp[1024];            // (K,V) pairs [c*64 + j2]
    int t = threadIdx.x;
    for (int i = t; i < 1024; i += 256) {
        int n = n0 + (i >> 4);
        float v = (n < NN) ? xf[n * 16 + (i & 15)] : 0.0f;
        Xd[i] = dup2(v);
    }
    const float* wk = (hid < 64) ? (kW2 + hid * 1024) : kb2;
    const float* wv = (hid < 64) ? (vW2 + hid * 1024) : vb2;
    for (int i = t; i < 1024; i += 256) Wp[i] = pk2(wk[i], wv[i]);
    __syncthreads();

#pragma unroll
    for (int r = 0; r < 16; r++) {
        int o = r * 256 + t;
        int nl = o >> 6, j2 = o & 63;
        u64 acc = 0ULL;
#pragma unroll
        for (int c = 0; c < 16; c++) acc = fma2_(Xd[nl * 16 + c], Wp[c * 64 + j2], acc);
        int n = n0 + nl;
        if (n < NN) {
            if (hid < 64) g_Qkv[(size_t)n * 4096 + hid * 64 + j2] = acc;
            else          g_Qbkv[n * 64 + j2] = acc;
        }
    }
}

// ---------------- K6: main edge kernel (one block per source node) ------------
// thread t: k = t>>3 (output channel), g = t&7 (hid-slice: hid = i*8+g).
__global__ void __launch_bounds__(128) k_edges(
    const float* __restrict__ sh, const float* __restrict__ emb,
    const float* __restrict__ elen,
    const float* __restrict__ kW1, const float* __restrict__ kb1,
    const float* __restrict__ vW1, const float* __restrict__ vb1,
    const int* __restrict__ eidx) {

    __shared__ u64 W1p[16 * 64];        // (K,V) pairs [b*64 + hid]
    __shared__ u64 b1p[64];
    __shared__ u64 h1p[4][64];          // silu(layer1) pairs per edge slot
    __shared__ float emb_s[4][16];
    __shared__ float sh_s[4][4];
    __shared__ float cut_s[4];
    __shared__ int   dst_s[4];

    int node = blockIdx.x;
    int t = threadIdx.x;
    int r0 = g_rowptr[node], deg = g_rowptr[node + 1] - r0;
    if (deg == 0) return;

    int k = t >> 3, g = t & 7;
    int head = k >> 2;

    for (int i = t; i < 1024; i += 128) W1p[i] = pk2(kW1[i], vW1[i]);
    for (int i = t; i < 64;   i += 128) b1p[i] = pk2(kb1[i], vb1[i]);

    // register-resident Q slice: q[i][s] = Qkv[node][hid=i*8+g][s*16+k]
    const u64* __restrict__ Qrow = g_Qkv + (size_t)node * 4096;
    u64 q[8][4];
#pragma unroll
    for (int i = 0; i < 8; i++)
#pragma unroll
        for (int s = 0; s < 4; s++)
            q[i][s] = Qrow[(i * 8 + g) * 64 + s * 16 + k];
    u64 qb[4];
#pragma unroll
    for (int s = 0; s < 4; s++) qb[s] = g_Qbkv[node * 64 + s * 16 + k];
    __syncthreads();

    for (int base = 0; base < deg; base += 4) {
        if (t < 4) {
            int idx = base + t;
            if (idx < deg) {
                int e = g_eorder[r0 + idx];
                dst_s[t] = eidx[EE + e];
                cut_s[t] = sigmoidf_(10.0f * (1.0f - elen[e] * INV_RADIUS));
#pragma unroll
                for (int b = 0; b < 16; b++) emb_s[t][b] = emb[e * 16 + b];
#pragma unroll
                for (int s = 0; s < 4; s++) sh_s[t][s] = sh[e * 4 + s];
            } else {
                dst_s[t] = -1; cut_s[t] = 0.0f;
#pragma unroll
                for (int b = 0; b < 16; b++) emb_s[t][b] = 0.0f;
#pragma unroll
                for (int s = 0; s < 4; s++) sh_s[t][s] = 0.0f;
            }
        }
        __syncthreads();

        // layer-1 MLP + silu for the 4 staged edges (paired K/V)
#pragma unroll
        for (int r = 0; r < 2; r++) {
            int o = r * 128 + t;
            int es = o >> 6, hid = o & 63;
            u64 acc = b1p[hid];
#pragma unroll
            for (int b = 0; b < 16; b++)
                acc = fma2_(dup2(emb_s[es][b]), W1p[b * 64 + hid], acc);
            float2 p = up2(acc);
            p.x = p.x * sigmoidf_(p.x);
            p.y = p.y * sigmoidf_(p.y);
            h1p[es][hid] = pk2(p.x, p.y);
        }
        __syncthreads();

#pragma unroll
        for (int es = 0; es < 4; es++) {
            u64 shd[4];
#pragma unroll
            for (int s = 0; s < 4; s++) shd[s] = dup2(sh_s[es][s]);
            u64 acc = 0ULL;
#pragma unroll
            for (int i = 0; i < 8; i++) {
                u64 dd = 0ULL;
#pragma unroll
                for (int s = 0; s < 4; s++) dd = fma2_(shd[s], q[i][s], dd);
                acc = fma2_(h1p[es][i * 8 + g], dd, acc);
            }
            float2 kv = up2(acc);
            // reduce over the 8 hid-slices (octet = consecutive lanes, same k)
            kv.x += __shfl_xor_sync(0xffffffffu, kv.x, 1);
            kv.y += __shfl_xor_sync(0xffffffffu, kv.y, 1);
            kv.x += __shfl_xor_sync(0xffffffffu, kv.x, 2);
            kv.y += __shfl_xor_sync(0xffffffffu, kv.y, 2);
            kv.x += __shfl_xor_sync(0xffffffffu, kv.x, 4);
            kv.y += __shfl_xor_sync(0xffffffffu, kv.y, 4);

            int ds = dst_s[es];
            float p = 0.0f;
            float kval = 0.0f, vval = 0.0f;
            if (g == 0 && ds >= 0) {
                u64 bacc = 0ULL;
#pragma unroll
                for (int s = 0; s < 4; s++) bacc = fma2_(shd[s], qb[s], bacc);
                float2 bb = up2(bacc);
                kval = (kv.x + bb.x) * TP_NORM;
                vval = (kv.y + bb.y) * TP_NORM;
                p = kval * g_qd[ds * 16 + k];
            }
            // reduce over the 4 heads' j (leaders are lanes 0,8,16,24 of warp)
            p += __shfl_xor_sync(0xffffffffu, p, 8);
            p += __shfl_xor_sync(0xffffffffu, p, 16);
            if (g == 0 && ds >= 0) {
                float logit = p * LOGIT_SCALE * cut_s[es];
                float ex = expf(logit);          // logits bounded small: no max-shift needed
                if ((t & 31) == 0) atomicAdd(&g_den[ds * 4 + head], ex);
                atomicAdd(&g_agg[ds * 16 + k], ex * vval);
            }
        }
        __syncthreads();
    }
}

// ---------------- K7: finalize per node (W_out, skip, FFN) --------------------
__global__ void k_final(const float* __restrict__ xf,
                        const float* __restrict__ Wout,
                        const float* __restrict__ Wf1,
                        const float* __restrict__ Wf2,
                        float* __restrict__ out) {
    __shared__ float Wo[256], F1[512], F2[512];
    int t = threadIdx.x;
    if (t < 256) Wo[t] = Wout[t];
    for (int i = t; i < 512; i += 256) { F1[i] = Wf1[i]; F2[i] = Wf2[i]; }
    __syncthreads();
    int n = blockIdx.x * 256 + t;
    if (n >= NN) return;

    float a[16];
#pragma unroll
    for (int k = 0; k < 16; k++) {
        float d = g_den[n * 4 + (k >> 2)];
        a[k] = (d > 0.0f) ? g_agg[n * 16 + k] / d : 0.0f;
    }
    float attn[16];
#pragma unroll
    for (int k = 0; k < 16; k++) {
        float s = xf[n * 16 + k];
#pragma unroll
        for (int jj = 0; jj < 16; jj++) s += a[jj] * Wo[jj * 16 + k];
        attn[k] = s;
    }
    float na[32];
#pragma unroll
    for (int jj = 0; jj < 32; jj++) {
        float f = 0.0f;
#pragma unroll
        for (int i = 0; i < 16; i++) f += attn[i] * F1[i * 32 + jj];
        na[jj] = f * sigmoidf_(fabsf(f));
    }
#pragma unroll
    for (int k = 0; k < 16; k++) {
        float o = attn[k];
#pragma unroll
        for (int jj = 0; jj < 32; jj++) o += na[jj] * F2[jj * 16 + k];
        out[n * 16 + k] = o;
    }
}

// ---------------- launch ------------------------------------------------------
extern "C" void kernel_launch(void* const* d_in, const int* in_sizes, int n_in,
                              void* d_out, int out_size) {
    const float* xf   = (const float*)d_in[0];
    const float* sh   = (const float*)d_in[1];
    const float* emb  = (const float*)d_in[2];
    const float* elen = (const float*)d_in[3];
    const float* Wq   = (const float*)d_in[4];
    const float* kW1  = (const float*)d_in[5];
    const float* kb1  = (const float*)d_in[6];
    const float* kW2  = (const float*)d_in[7];
    const float* kb2  = (const float*)d_in[8];
    const float* vW1  = (const float*)d_in[9];
    const float* vb1  = (const float*)d_in[10];
    const float* vW2  = (const float*)d_in[11];
    const float* vb2  = (const float*)d_in[12];
    const float* Wdot = (const float*)d_in[13];
    const float* Wout = (const float*)d_in[14];
    const float* Wf1  = (const float*)d_in[15];
    const float* Wf2  = (const float*)d_in[16];
    const int*   eidx = (const int*)d_in[17];
    float* out = (float*)d_out;

    k_init<<<(NN * CC + 255) / 256, 256>>>();
    k_hist<<<(EE + 255) / 256, 256>>>(eidx);
    k_scan<<<1, 1024>>>();
    k_scatter<<<(EE + 255) / 256, 256>>>(eidx);
    k_qprojd<<<(NN + 15) / 16, 256>>>(xf, Wq, Wdot);
    dim3 g5((NN + 63) / 64, 65);
    k_qweights<<<g5, 256>>>(xf, kW2, kb2, vW2, vb2);
    k_edges<<<NN, 128>>>(sh, emb, elen, kW1, kb1, vW1, vb1, eidx);
    k_final<<<(NN + 255) / 256, 256>>>(xf, Wout, Wf1, Wf2, out);
}

// round 4
// speedup vs baseline: 1.3146x; 1.0659x over previous
#include <cuda_runtime.h>
#include <cuda_fp16.h>
#include <math.h>

#define NN 10000
#define EE 100000
#define TP_NORM 0.125f       // 1/sqrt(C*S)
#define LOGIT_SCALE 0.125f   // DOT_NORM * SCALE
#define INV_RADIUS 0.2f

typedef unsigned long long u64;
typedef unsigned int u32;

// ---------------- scratch ----------------------------------------------------
__device__ u32  g_QhK[(size_t)NN * 2048];   // half2 pairs (hid 2h,2h+1): [n][(s*16+k)*32 + h]
__device__ u32  g_QhV[(size_t)NN * 2048];
__device__ u64  g_Qbkv[NN * 64];            // (K,V) f32 pairs: [n][s*16+k]
__device__ u64  g_WtK[32768];               // W2 transposed: [(c*64+sk)*32 + h] = (W2[2h], W2[2h+1])
__device__ u64  g_WtV[32768];
__device__ u32  g_h1K[(size_t)EE * 32];     // half2 pairs per sorted edge pos
__device__ u32  g_h1V[(size_t)EE * 32];
__device__ float2 g_dc[EE];                 // (dst bitcast, cutoff) per sorted pos
__device__ float4 g_sh4[EE];                // sh per sorted pos
__device__ float g_qd[NN * 16];             // q @ W_dot
__device__ int   g_deg[NN];
__device__ int   g_rowptr[NN + 1];
__device__ int   g_cursor[NN];
__device__ int   g_eorder[EE];
__device__ float g_den[NN * 4];
__device__ float g_agg[NN * 16];

__device__ __forceinline__ float sigmoidf_(float x) { return 1.0f / (1.0f + expf(-x)); }
__device__ __forceinline__ u64 pk2(float lo, float hi) {
    u64 r; asm("mov.b64 %0, {%1, %2};" : "=l"(r) : "f"(lo), "f"(hi)); return r;
}
__device__ __forceinline__ float2 up2(u64 v) {
    float2 f; asm("mov.b64 {%0, %1}, %2;" : "=f"(f.x), "=f"(f.y) : "l"(v)); return f;
}
__device__ __forceinline__ u64 dup2(float x) { return pk2(x, x); }
__device__ __forceinline__ u64 fma2_(u64 a, u64 b, u64 c) {
    u64 d; asm("fma.rn.f32x2 %0, %1, %2, %3;" : "=l"(d) : "l"(a), "l"(b), "l"(c)); return d;
}
__device__ __forceinline__ u32 pack_h2(float lo, float hi) {
    __half2 h = __floats2half2_rn(lo, hi);
    return *reinterpret_cast<u32*>(&h);
}
__device__ __forceinline__ u64 unpack_h2(u32 v) {
    __half2 h = *reinterpret_cast<__half2*>(&v);
    float2 f = __half22float2(h);           // .x = lo
    return pk2(f.x, f.y);
}

// ---------------- K1: degree histogram by src ---------------------------------
__global__ void k_hist(const int* __restrict__ eidx) {
    int e = blockIdx.x * 256 + threadIdx.x;
    if (e < EE) atomicAdd(&g_deg[eidx[e]], 1);
}

// ---------------- K2: exclusive scan (single block) + re-zero deg -------------
__global__ void k_scan() {
    __shared__ int ps[1024];
    const int PER = 10;
    int t = threadIdx.x;
    int start = t * PER;
    int sum = 0;
    int local[PER];
    for (int i = 0; i < PER; i++) {
        int idx = start + i;
        local[i] = (idx < NN) ? g_deg[idx] : 0;
        if (idx < NN) g_deg[idx] = 0;        // re-zero for next replay
        sum += local[i];
    }
    ps[t] = sum;
    __syncthreads();
    for (int off = 1; off < 1024; off <<= 1) {
        int add = (t >= off) ? ps[t - off] : 0;
        __syncthreads();
        ps[t] += add;
        __syncthreads();
    }
    int base = ps[t] - sum;
    for (int i = 0; i < PER; i++) {
        int idx = start + i;
        if (idx < NN) { g_rowptr[idx] = base; g_cursor[idx] = base; base += local[i]; }
    }
    if (t == 1023) g_rowptr[NN] = ps[1023];
}

// ---------------- K3: scatter edges grouped by src ----------------------------
__global__ void k_scatter(const int* __restrict__ eidx) {
    int e = blockIdx.x * 256 + threadIdx.x;
    if (e < EE) {
        int s = eidx[e];
        int pos = atomicAdd(&g_cursor[s], 1);
        g_eorder[pos] = e;
    }
}

// ---------------- K4: transpose W2 into hid-pair u64 layout -------------------
__global__ void k_transW(const float* __restrict__ kW2, const float* __restrict__ vW2) {
    int i = blockIdx.x * 256 + threadIdx.x;
    int tz = blockIdx.y;
    const float* W = tz ? vW2 : kW2;
    u64* out = tz ? g_WtV : g_WtK;
    if (i < 32768) {
        int h = i & 31, csk = i >> 5;
        out[i] = pk2(W[(2 * h) * 1024 + csk], W[(2 * h + 1) * 1024 + csk]);
    }
}

// ---------------- K5: qd = (x@Wq)@Wdot per node, plus bias part Qb ------------
__global__ void k_qprojd(const float* __restrict__ xf, const float* __restrict__ Wq,
                         const float* __restrict__ Wdot,
                         const float* __restrict__ kb2, const float* __restrict__ vb2) {
    __shared__ float Wqs[256], Wds[16], Xs[16][16], B2K[1024], B2V[1024];
    int t = threadIdx.x;
    if (t < 256) Wqs[t] = Wq[t];
    if (t < 16)  Wds[t] = Wdot[t];
    for (int i = t; i < 1024; i += 256) { B2K[i] = kb2[i]; B2V[i] = vb2[i]; }
    int n0 = blockIdx.x * 16;
    { int nl = t >> 4, c = t & 15; Xs[nl][c] = xf[(n0 + nl) * 16 + c]; }
    __syncthreads();
    int nl = t >> 4, k = t & 15;
    int n = n0 + nl;
    int head = k >> 2, j = k & 3;
    float qd = 0.0f;
#pragma unroll
    for (int i2 = 0; i2 < 4; i2++) {
        float q = 0.0f;
#pragma unroll
        for (int c = 0; c < 16; c++) q += Xs[nl][c] * Wqs[c * 16 + head * 4 + i2];
        qd += q * Wds[i2 * 4 + j];
    }
    g_qd[n * 16 + k] = qd;
#pragma unroll
    for (int s = 0; s < 4; s++) {
        float aK = 0.0f, aV = 0.0f;
#pragma unroll
        for (int c = 0; c < 16; c++) {
            float x = Xs[nl][c];
            aK += x * B2K[c * 64 + s * 16 + k];
            aV += x * B2V[c * 64 + s * 16 + k];
        }
        g_Qbkv[n * 64 + s * 16 + k] = pk2(aK, aV);
    }
}

// ---------------- K6: per-node Q tensors (fp16 out, W register-cached) --------
// grid (157, 4, 2): 64 nodes x 16 hids (8 pairs) x {K,V}. 512 threads: hp=t&7, sk=t>>3.
__global__ void __launch_bounds__(512) k_qweights(const float* __restrict__ xf) {
    int n0 = blockIdx.x * 64;
    int h8 = blockIdx.y * 8;
    int tz = blockIdx.z;
    __shared__ u64 Xd[64 * 16];
    int t = threadIdx.x;
    for (int i = t; i < 1024; i += 512) {
        int n = n0 + (i >> 4);
        Xd[i] = dup2((n < NN) ? xf[n * 16 + (i & 15)] : 0.0f);
    }
    __syncthreads();
    int hp = t & 7, sk = t >> 3;
    const u64* __restrict__ Wt = tz ? g_WtV : g_WtK;
    u32* __restrict__ Qh = tz ? g_QhV : g_QhK;
    u64 wreg[16];
#pragma unroll
    for (int c = 0; c < 16; c++) wreg[c] = __ldg(&Wt[(c * 64 + sk) * 32 + h8 + hp]);
#pragma unroll 4
    for (int n = 0; n < 64; n++) {
        u64 acc = 0ULL;
#pragma unroll
        for (int c = 0; c < 16; c++) acc = fma2_(Xd[n * 16 + c], wreg[c], acc);
        if (n0 + n < NN) {
            float2 f = up2(acc);
            Qh[(size_t)(n0 + n) * 2048 + sk * 32 + h8 + hp] = pack_h2(f.x, f.y);
        }
    }
}

// ---------------- K7: per-edge radial MLP (h1) + meta, in sorted order --------
// grid 6250 x 256: 16 edges per block. thread: h=t&31, tz=(t>>5)&1, elg=t>>6.
__global__ void __launch_bounds__(256) k_mlp(
    const float* __restrict__ sh, const float* __restrict__ emb,
    const float* __restrict__ elen,
    const float* __restrict__ kW1, const float* __restrict__ kb1,
    const float* __restrict__ vW1, const float* __restrict__ vb1,
    const int* __restrict__ eidx) {
    __shared__ float emb_s[16][16];
    __shared__ int   e_s[16];
    int t = threadIdx.x;
    int pos0 = blockIdx.x * 16;
    if (t < 16) {
        int e = g_eorder[pos0 + t];
        e_s[t] = e;
        int ds = eidx[EE + e];
        float cut = sigmoidf_(10.0f * (1.0f - elen[e] * INV_RADIUS));
        g_dc[pos0 + t] = make_float2(__int_as_float(ds), cut);
        g_sh4[pos0 + t] = *reinterpret_cast<const float4*>(sh + e * 4);
    }
    __syncthreads();
    { int el = t >> 4, b = t & 15; emb_s[el][b] = emb[e_s[el] * 16 + b]; }
    __syncthreads();
    int h = t & 31, tz = (t >> 5) & 1, elg = t >> 6;
    const u64* __restrict__ W1 = reinterpret_cast<const u64*>(tz ? vW1 : kW1);
    const u64* __restrict__ b1 = reinterpret_cast<const u64*>(tz ? vb1 : kb1);
    u32* __restrict__ H = tz ? g_h1V : g_h1K;
    u64 w1r[16];
#pragma unroll
    for (int b = 0; b < 16; b++) w1r[b] = __ldg(&W1[b * 32 + h]);
    u64 bb = __ldg(&b1[h]);
#pragma unroll
    for (int r = 0; r < 4; r++) {
        int el = r * 4 + elg;
        u64 acc = bb;
#pragma unroll
        for (int b = 0; b < 16; b++) acc = fma2_(dup2(emb_s[el][b]), w1r[b], acc);
        float2 f = up2(acc);
        f.x = f.x * sigmoidf_(f.x);
        f.y = f.y * sigmoidf_(f.y);
        H[(size_t)(pos0 + el) * 32 + h] = pack_h2(f.x, f.y);
    }
}

// ---------------- K8: main edge contraction (one block per source node) -------
// 256 threads: k = t>>4 (channel), g = t&15 (hid-pair slice, pair h = i*16+g).
__global__ void __launch_bounds__(256) k_edges(const int* __restrict__ dummy) {
    __shared__ float4 shs[8];
    __shared__ int    dsts[8];
    __shared__ float  cuts[8];
    __shared__ float2 kvs[8][16];
    __shared__ float  exs[8][4];

    int node = blockIdx.x;
    int t = threadIdx.x;
    int r0 = g_rowptr[node], deg = g_rowptr[node + 1] - r0;
    if (deg == 0) return;

    int k = t >> 4, g = t & 15;

    const u32* __restrict__ QK = g_QhK + (size_t)node * 2048;
    const u32* __restrict__ QV = g_QhV + (size_t)node * 2048;
    u64 qK[2][4], qV[2][4];
#pragma unroll
    for (int i = 0; i < 2; i++)
#pragma unroll
        for (int s = 0; s < 4; s++) {
            int idx = (s * 16 + k) * 32 + i * 16 + g;
            qK[i][s] = unpack_h2(__ldg(&QK[idx]));
            qV[i][s] = unpack_h2(__ldg(&QV[idx]));
        }
    u64 qb[4];
    if (g == 0) {
#pragma unroll
        for (int s = 0; s < 4; s++) qb[s] = g_Qbkv[node * 64 + s * 16 + k];
    }

    for (int base = 0; base < deg; base += 8) {
        if (t < 8) {
            int idx = base + t;
            if (idx < deg) {
                float2 dc = g_dc[r0 + idx];
                dsts[t] = __float_as_int(dc.x);
                cuts[t] = dc.y;
                shs[t]  = g_sh4[r0 + idx];
            } else dsts[t] = -1;
        }
        __syncthreads();
        int nval = min(8, deg - base);
        for (int es = 0; es < nval; es++) {
            int pos = r0 + base + es;
            float4 s4 = shs[es];
            u64 sh0 = dup2(s4.x), sh1 = dup2(s4.y), sh2 = dup2(s4.z), sh3 = dup2(s4.w);
            u64 accK = 0ULL, accV = 0ULL;
#pragma unroll
            for (int i = 0; i < 2; i++) {
                u64 ddK = fma2_(sh0, qK[i][0], 0ULL);
                ddK = fma2_(sh1, qK[i][1], ddK);
                ddK = fma2_(sh2, qK[i][2], ddK);
                ddK = fma2_(sh3, qK[i][3], ddK);
                u64 ddV = fma2_(sh0, qV[i][0], 0ULL);
                ddV = fma2_(sh1, qV[i][1], ddV);
                ddV = fma2_(sh2, qV[i][2], ddV);
                ddV = fma2_(sh3, qV[i][3], ddV);
                u64 hK = unpack_h2(__ldg(&g_h1K[(size_t)pos * 32 + i * 16 + g]));
                u64 hV = unpack_h2(__ldg(&g_h1V[(size_t)pos * 32 + i * 16 + g]));
                accK = fma2_(hK, ddK, accK);
                accV = fma2_(hV, ddV, accV);
            }
            float2 aK = up2(accK), aV = up2(accV);
            float kv_k = aK.x + aK.y;
            float kv_v = aV.x + aV.y;
            kv_k += __shfl_xor_sync(0xffffffffu, kv_k, 1);
            kv_v += __shfl_xor_sync(0xffffffffu, kv_v, 1);
            kv_k += __shfl_xor_sync(0xffffffffu, kv_k, 2);
            kv_v += __shfl_xor_sync(0xffffffffu, kv_v, 2);
            kv_k += __shfl_xor_sync(0xffffffffu, kv_k, 4);
            kv_v += __shfl_xor_sync(0xffffffffu, kv_v, 4);
            kv_k += __shfl_xor_sync(0xffffffffu, kv_k, 8);
            kv_v += __shfl_xor_sync(0xffffffffu, kv_v, 8);
            if (g == 0) {
                u64 bacc = fma2_(sh0, qb[0], 0ULL);
                bacc = fma2_(sh1, qb[1], bacc);
                bacc = fma2_(sh2, qb[2], bacc);
                bacc = fma2_(sh3, qb[3], bacc);
                float2 bb = up2(bacc);
                kvs[es][k] = make_float2((kv_k + bb.x) * TP_NORM, (kv_v + bb.y) * TP_NORM);
            }
        }
        __syncthreads();
        if (t < 32) {
            int es = t >> 2, hd = t & 3;
            float ex = 0.0f;
            int ds = dsts[es];
            if (ds >= 0) {
                float4 qd = *reinterpret_cast<const float4*>(g_qd + ds * 16 + hd * 4);
                const float2* kr = &kvs[es][hd * 4];
                float lg = kr[0].x * qd.x + kr[1].x * qd.y + kr[2].x * qd.z + kr[3].x * qd.w;
                ex = expf(lg * LOGIT_SCALE * cuts[es]);
                atomicAdd(&g_den[ds * 4 + hd], ex);
            }
            exs[es][hd] = ex;
        }
        __syncthreads();
        if (t < 128) {
            int es = t >> 4, kk = t & 15;
            int ds = dsts[es];
            if (ds >= 0) atomicAdd(&g_agg[ds * 16 + kk], exs[es][kk >> 2] * kvs[es][kk].y);
        }
        __syncthreads();
    }
}

// ---------------- K9: finalize per node (W_out, skip, FFN) + re-zero ----------
__global__ void k_final(const float* __restrict__ xf,
                        const float* __restrict__ Wout,
                        const float* __restrict__ Wf1,
                        const float* __restrict__ Wf2,
                        float* __restrict__ out) {
    __shared__ float Wo[256], F1[512], F2[512];
    int t = threadIdx.x;
    if (t < 256) Wo[t] = Wout[t];
    for (int i = t; i < 512; i += 256) { F1[i] = Wf1[i]; F2[i] = Wf2[i]; }
    __syncthreads();
    int n = blockIdx.x * 256 + t;
    if (n >= NN) return;

    float a[16];
#pragma unroll
    for (int k = 0; k < 16; k++) {
        float d = g_den[n * 4 + (k >> 2)];
        a[k] = (d > 0.0f) ? g_agg[n * 16 + k] / d : 0.0f;
        g_agg[n * 16 + k] = 0.0f;            // re-zero for next replay
    }
#pragma unroll
    for (int h = 0; h < 4; h++) g_den[n * 4 + h] = 0.0f;
    float attn[16];
#pragma unroll
    for (int k = 0; k < 16; k++) {
        float s = xf[n * 16 + k];
#pragma unroll
        for (int jj = 0; jj < 16; jj++) s += a[jj] * Wo[jj * 16 + k];
        attn[k] = s;
    }
    float na[32];
#pragma unroll
    for (int jj = 0; jj < 32; jj++) {
        float f = 0.0f;
#pragma unroll
        for (int i = 0; i < 16; i++) f += attn[i] * F1[i * 32 + jj];
        na[jj] = f * sigmoidf_(fabsf(f));
    }
#pragma unroll
    for (int k = 0; k < 16; k++) {
        float o = attn[k];
#pragma unroll
        for (int jj = 0; jj < 32; jj++) o += na[jj] * F2[jj * 16 + k];
        out[n * 16 + k] = o;
    }
}

// ---------------- launch ------------------------------------------------------
extern "C" void kernel_launch(void* const* d_in, const int* in_sizes, int n_in,
                              void* d_out, int out_size) {
    const float* xf   = (const float*)d_in[0];
    const float* sh   = (const float*)d_in[1];
    const float* emb  = (const float*)d_in[2];
    const float* elen = (const float*)d_in[3];
    const float* Wq   = (const float*)d_in[4];
    const float* kW1  = (const float*)d_in[5];
    const float* kb1  = (const float*)d_in[6];
    const float* kW2  = (const float*)d_in[7];
    const float* kb2  = (const float*)d_in[8];
    const float* vW1  = (const float*)d_in[9];
    const float* vb1  = (const float*)d_in[10];
    const float* vW2  = (const float*)d_in[11];
    const float* vb2  = (const float*)d_in[12];
    const float* Wdot = (const float*)d_in[13];
    const float* Wout = (const float*)d_in[14];
    const float* Wf1  = (const float*)d_in[15];
    const float* Wf2  = (const float*)d_in[16];
    const int*   eidx = (const int*)d_in[17];
    float* out = (float*)d_out;

    k_hist<<<(EE + 255) / 256, 256>>>(eidx);
    k_scan<<<1, 1024>>>();
    k_scatter<<<(EE + 255) / 256, 256>>>(eidx);
    dim3 gW(128, 2);
    k_transW<<<gW, 256>>>(kW2, vW2);
    k_qprojd<<<NN / 16, 256>>>(xf, Wq, Wdot, kb2, vb2);
    dim3 gQ((NN + 63) / 64, 4, 2);
    k_qweights<<<gQ, 512>>>(xf);
    k_mlp<<<EE / 16, 256>>>(sh, emb, elen, kW1, kb1, vW1, vb1, eidx);
    k_edges<<<NN, 256>>>(eidx);
    k_final<<<(NN + 255) / 256, 256>>>(xf, Wout, Wf1, Wf2, out);
}

// round 6
// speedup vs baseline: 1.4869x; 1.1311x over previous
#include <cuda_runtime.h>
#include <cuda_fp16.h>
#include <math.h>

#define NN 10000
#define EE 100000
#define TP_NORM 0.125f       // 1/sqrt(C*S)
#define LOGIT_SCALE 0.125f   // DOT_NORM * SCALE
#define INV_RADIUS 0.2f

typedef unsigned long long u64;
typedef unsigned int u32;

// ---------------- scratch ----------------------------------------------------
__device__ u32  g_QhK[(size_t)NN * 2048];   // half2 pairs (hid 2h,2h+1): [n][(s*16+k)*32 + h]
__device__ u32  g_QhV[(size_t)NN * 2048];
__device__ u64  g_Qbkv[NN * 64];            // (K,V) f32 pairs: [n][s*16+k]
__device__ u64  g_WtK[32768];               // W2 transposed: [(c*64+sk)*32 + h]
__device__ u64  g_WtV[32768];
__device__ u32  g_h1K[(size_t)EE * 32];     // half2 pairs, ORIGINAL edge order
__device__ u32  g_h1V[(size_t)EE * 32];
__device__ float2 g_dc[EE];                 // (dst bitcast, cutoff), original order
__device__ float4 g_sh4[EE];                // sh, original order
__device__ float g_qd[NN * 16];             // q @ W_dot
__device__ int   g_deg[NN];
__device__ int   g_rowptr[NN + 1];
__device__ int   g_cursor[NN];
__device__ int   g_eorder[EE];
__device__ float g_den[NN * 4];
__device__ float g_agg[NN * 16];

__device__ __forceinline__ float sigmoidf_(float x) { return 1.0f / (1.0f + expf(-x)); }
__device__ __forceinline__ u64 pk2(float lo, float hi) {
    u64 r; asm("mov.b64 %0, {%1, %2};" : "=l"(r) : "f"(lo), "f"(hi)); return r;
}
__device__ __forceinline__ float2 up2(u64 v) {
    float2 f; asm("mov.b64 {%0, %1}, %2;" : "=f"(f.x), "=f"(f.y) : "l"(v)); return f;
}
__device__ __forceinline__ u64 dup2(float x) { return pk2(x, x); }
__device__ __forceinline__ u64 fma2_(u64 a, u64 b, u64 c) {
    u64 d; asm("fma.rn.f32x2 %0, %1, %2, %3;" : "=l"(d) : "l"(a), "l"(b), "l"(c)); return d;
}
__device__ __forceinline__ u32 pack_h2(float lo, float hi) {
    __half2 h = __floats2half2_rn(lo, hi);
    return *reinterpret_cast<u32*>(&h);
}
__device__ __forceinline__ u64 unpack_h2(u32 v) {
    __half2 h = *reinterpret_cast<__half2*>(&v);
    float2 f = __half22float2(h);
    return pk2(f.x, f.y);
}

// ================= PRO1: fused independent prologue (256-thread blocks) ======
// block ranges: [0,391) hist | [391,647) transW | [647,1272) qprojd | [1272,7522) mlp
#define PRO1_HIST   391
#define PRO1_TRANSW (PRO1_HIST + 256)
#define PRO1_QPROJD (PRO1_TRANSW + 625)
#define PRO1_TOTAL  (PRO1_QPROJD + 6250)

__global__ void __launch_bounds__(256) k_pro1(
    const int* __restrict__ eidx,
    const float* __restrict__ kW2, const float* __restrict__ vW2,
    const float* __restrict__ xf,  const float* __restrict__ Wq,
    const float* __restrict__ Wdot,
    const float* __restrict__ kb2, const float* __restrict__ vb2,
    const float* __restrict__ sh,  const float* __restrict__ emb,
    const float* __restrict__ elen,
    const float* __restrict__ kW1, const float* __restrict__ kb1,
    const float* __restrict__ vW1, const float* __restrict__ vb1) {

    int blk = blockIdx.x;
    int t = threadIdx.x;

    if (blk < PRO1_HIST) {
        // ---- degree histogram by src ----
        int e = blk * 256 + t;
        if (e < EE) atomicAdd(&g_deg[eidx[e]], 1);

    } else if (blk < PRO1_TRANSW) {
        // ---- W2 transpose into hid-pair u64 layout ----
        int b = blk - PRO1_HIST;            // 0..255
        int tz = b >> 7;                    // 0..1
        int i = (b & 127) * 256 + t;        // 0..32767
        const float* W = tz ? vW2 : kW2;
        u64* out = tz ? g_WtV : g_WtK;
        int h = i & 31, csk = i >> 5;
        out[i] = pk2(W[(2 * h) * 1024 + csk], W[(2 * h + 1) * 1024 + csk]);

    } else if (blk < PRO1_QPROJD) {
        // ---- qd = (x@Wq)@Wdot + bias part Qb ----
        __shared__ float Wqs[256], Wds[16], Xs[16][16], B2K[1024], B2V[1024];
        if (t < 256) Wqs[t] = Wq[t];
        if (t < 16)  Wds[t] = Wdot[t];
        for (int i = t; i < 1024; i += 256) { B2K[i] = kb2[i]; B2V[i] = vb2[i]; }
        int n0 = (blk - PRO1_TRANSW) * 16;
        { int nl = t >> 4, c = t & 15; Xs[nl][c] = xf[(n0 + nl) * 16 + c]; }
        __syncthreads();
        int nl = t >> 4, k = t & 15;
        int n = n0 + nl;
        int head = k >> 2, j = k & 3;
        float qd = 0.0f;
#pragma unroll
        for (int i2 = 0; i2 < 4; i2++) {
            float q = 0.0f;
#pragma unroll
            for (int c = 0; c < 16; c++) q += Xs[nl][c] * Wqs[c * 16 + head * 4 + i2];
            qd += q * Wds[i2 * 4 + j];
        }
        g_qd[n * 16 + k] = qd;
#pragma unroll
        for (int s = 0; s < 4; s++) {
            float aK = 0.0f, aV = 0.0f;
#pragma unroll
            for (int c = 0; c < 16; c++) {
                float x = Xs[nl][c];
                aK += x * B2K[c * 64 + s * 16 + k];
                aV += x * B2V[c * 64 + s * 16 + k];
            }
            g_Qbkv[n * 64 + s * 16 + k] = pk2(aK, aV);
        }

    } else {
        // ---- per-edge radial MLP + meta, original edge order ----
        __shared__ float emb_s[16][16];
        int e0 = (blk - PRO1_QPROJD) * 16;
        { int el = t >> 4, b = t & 15; emb_s[el][b] = emb[(e0 + el) * 16 + b]; }
        if (t < 16) {
            int e = e0 + t;
            int ds = eidx[EE + e];
            float cut = sigmoidf_(10.0f * (1.0f - elen[e] * INV_RADIUS));
            g_dc[e] = make_float2(__int_as_float(ds), cut);
            g_sh4[e] = *reinterpret_cast<const float4*>(sh + e * 4);
        }
        __syncthreads();
        int h = t & 31, tz = (t >> 5) & 1, elg = t >> 6;
        const u64* __restrict__ W1 = reinterpret_cast<const u64*>(tz ? vW1 : kW1);
        const u64* __restrict__ b1 = reinterpret_cast<const u64*>(tz ? vb1 : kb1);
        u32* __restrict__ H = tz ? g_h1V : g_h1K;
        u64 w1r[16];
#pragma unroll
        for (int b = 0; b < 16; b++) w1r[b] = __ldg(&W1[b * 32 + h]);
        u64 bb = __ldg(&b1[h]);
#pragma unroll
        for (int r = 0; r < 4; r++) {
            int el = r * 4 + elg;
            u64 acc = bb;
#pragma unroll
            for (int b = 0; b < 16; b++) acc = fma2_(dup2(emb_s[el][b]), w1r[b], acc);
            float2 f = up2(acc);
            f.x = f.x * sigmoidf_(f.x);
            f.y = f.y * sigmoidf_(f.y);
            H[(size_t)(e0 + el) * 32 + h] = pack_h2(f.x, f.y);
        }
    }
}

// ================= PRO2: scan (block 0) + qweights (blocks 1..1256) ==========
__global__ void __launch_bounds__(512) k_pro2(const float* __restrict__ xf) {
    int blk = blockIdx.x;
    int t = threadIdx.x;

    if (blk == 0) {
        // ---- exclusive scan over degrees (512 threads, 20 each) + re-zero ----
        __shared__ int ps[512];
        const int PER = 20;                 // 512*20 = 10240 >= NN
        int start = t * PER;
        int sum = 0;
        int local[PER];
        for (int i = 0; i < PER; i++) {
            int idx = start + i;
            local[i] = (idx < NN) ? g_deg[idx] : 0;
            if (idx < NN) g_deg[idx] = 0;   // re-zero for next replay
            sum += local[i];
        }
        ps[t] = sum;
        __syncthreads();
        for (int off = 1; off < 512; off <<= 1) {
            int add = (t >= off) ? ps[t - off] : 0;
            __syncthreads();
            ps[t] += add;
            __syncthreads();
        }
        int base = ps[t] - sum;
        for (int i = 0; i < PER; i++) {
            int idx = start + i;
            if (idx < NN) { g_rowptr[idx] = base; g_cursor[idx] = base; base += local[i]; }
        }
        if (t == 511) g_rowptr[NN] = ps[511];

    } else {
        // ---- per-node Q tensors (fp16 out, W register-cached) ----
        int b = blk - 1;                    // 0..1255
        int n0 = (b % 157) * 64;
        int h8 = ((b / 157) & 3) * 8;
        int tz = b / 628;
        __shared__ u64 Xd[64 * 16];
        for (int i = t; i < 1024; i += 512) {
            int n = n0 + (i >> 4);
            Xd[i] = dup2((n < NN) ? xf[n * 16 + (i & 15)] : 0.0f);
        }
        __syncthreads();
        int hp = t & 7, sk = t >> 3;
        const u64* __restrict__ Wt = tz ? g_WtV : g_WtK;
        u32* __restrict__ Qh = tz ? g_QhV : g_QhK;
        u64 wreg[16];
#pragma unroll
        for (int c = 0; c < 16; c++) wreg[c] = __ldg(&Wt[(c * 64 + sk) * 32 + h8 + hp]);
#pragma unroll 4
        for (int n = 0; n < 64; n++) {
            u64 acc = 0ULL;
#pragma unroll
            for (int c = 0; c < 16; c++) acc = fma2_(Xd[n * 16 + c], wreg[c], acc);
            if (n0 + n < NN) {
                float2 f = up2(acc);
                Qh[(size_t)(n0 + n) * 2048 + sk * 32 + h8 + hp] = pack_h2(f.x, f.y);
            }
        }
    }
}

// ---------------- scatter edges grouped by src --------------------------------
__global__ void k_scatter(const int* __restrict__ eidx) {
    int e = blockIdx.x * 256 + threadIdx.x;
    if (e < EE) {
        int s = eidx[e];
        int pos = atomicAdd(&g_cursor[s], 1);
        g_eorder[pos] = e;
    }
}

// ---------------- main edge contraction (one block per source node) -----------
// 256 threads: k = t>>4 (channel), g = t&15 (hid-pair slice, pair h = i*16+g).
__global__ void __launch_bounds__(256) k_edges() {
    __shared__ int    dstS[8];
    __shared__ float  cutS[8];
    __shared__ float4 shS[8];
    __shared__ u32    h1Ks[8][32];
    __shared__ u32    h1Vs[8][32];
    __shared__ float2 kvs[8][16];

    int node = blockIdx.x;
    int t = threadIdx.x;
    int r0 = g_rowptr[node], deg = g_rowptr[node + 1] - r0;
    if (deg == 0) return;

    int k = t >> 4, g = t & 15;

    const u32* __restrict__ QK = g_QhK + (size_t)node * 2048;
    const u32* __restrict__ QV = g_QhV + (size_t)node * 2048;
    u64 qK[2][4], qV[2][4];
#pragma unroll
    for (int i = 0; i < 2; i++)
#pragma unroll
        for (int s = 0; s < 4; s++) {
            int idx = (s * 16 + k) * 32 + i * 16 + g;
            qK[i][s] = unpack_h2(__ldg(&QK[idx]));
            qV[i][s] = unpack_h2(__ldg(&QV[idx]));
        }
    u64 qb[4];
    if (g == 0) {
#pragma unroll
        for (int s = 0; s < 4; s++) qb[s] = g_Qbkv[node * 64 + s * 16 + k];
    }

    for (int base = 0; base < deg; base += 8) {
        // ---- single staging phase (all 256 threads) ----
        {
            int es = t >> 5, h = t & 31;
            int idx = base + es;
            int e = (idx < deg) ? __ldg(&g_eorder[r0 + idx]) : -1;
            if (e >= 0) {
                h1Ks[es][h] = __ldg(&g_h1K[(size_t)e * 32 + h]);
                h1Vs[es][h] = __ldg(&g_h1V[(size_t)e * 32 + h]);
            } else {
                h1Ks[es][h] = 0u;
                h1Vs[es][h] = 0u;
            }
            if (t < 8) {
                int idx2 = base + t;
                if (idx2 < deg) {
                    int e2 = __ldg(&g_eorder[r0 + idx2]);
                    float2 dc = g_dc[e2];
                    dstS[t] = __float_as_int(dc.x);
                    cutS[t] = dc.y;
                    shS[t]  = g_sh4[e2];
                } else {
                    dstS[t] = -1;
                    shS[t] = make_float4(0.f, 0.f, 0.f, 0.f);
                }
            }
        }
        __syncthreads();

        // ---- fully-unrolled compute over 8 (padded) edge slots ----
#pragma unroll
        for (int es = 0; es < 8; es++) {
            float4 s4 = shS[es];
            u64 sh0 = dup2(s4.x), sh1 = dup2(s4.y), sh2 = dup2(s4.z), sh3 = dup2(s4.w);
            u64 accK = 0ULL, accV = 0ULL;
#pragma unroll
            for (int i = 0; i < 2; i++) {
                u64 ddK = fma2_(sh0, qK[i][0], 0ULL);
                ddK = fma2_(sh1, qK[i][1], ddK);
                ddK = fma2_(sh2, qK[i][2], ddK);
                ddK = fma2_(sh3, qK[i][3], ddK);
                u64 ddV = fma2_(sh0, qV[i][0], 0ULL);
                ddV = fma2_(sh1, qV[i][1], ddV);
                ddV = fma2_(sh2, qV[i][2], ddV);
                ddV = fma2_(sh3, qV[i][3], ddV);
                u64 hK = unpack_h2(h1Ks[es][i * 16 + g]);
                u64 hV = unpack_h2(h1Vs[es][i * 16 + g]);
                accK = fma2_(hK, ddK, accK);
                accV = fma2_(hV, ddV, accV);
            }
            float2 aK = up2(accK), aV = up2(accV);
            float kv_k = aK.x + aK.y;
            float kv_v = aV.x + aV.y;
            kv_k += __shfl_xor_sync(0xffffffffu, kv_k, 1);
            kv_v += __shfl_xor_sync(0xffffffffu, kv_v, 1);
            kv_k += __shfl_xor_sync(0xffffffffu, kv_k, 2);
            kv_v += __shfl_xor_sync(0xffffffffu, kv_v, 2);
            kv_k += __shfl_xor_sync(0xffffffffu, kv_k, 4);
            kv_v += __shfl_xor_sync(0xffffffffu, kv_v, 4);
            kv_k += __shfl_xor_sync(0xffffffffu, kv_k, 8);
            kv_v += __shfl_xor_sync(0xffffffffu, kv_v, 8);
            if (g == 0) {
                u64 bacc = fma2_(sh0, qb[0], 0ULL);
                bacc = fma2_(sh1, qb[1], bacc);
                bacc = fma2_(sh2, qb[2], bacc);
                bacc = fma2_(sh3, qb[3], bacc);
                float2 bb = up2(bacc);
                kvs[es][k] = make_float2((kv_k + bb.x) * TP_NORM, (kv_v + bb.y) * TP_NORM);
            }
        }
        __syncthreads();

        // ---- merged epilogue: redundant ex per kk, one sync ----
        if (t < 128) {
            int es = t >> 4, kk = t & 15, hd = kk >> 2;
            int ds = dstS[es];
            if (ds >= 0) {
                float4 qd = *reinterpret_cast<const float4*>(g_qd + ds * 16 + hd * 4);
                const float2* kr = &kvs[es][hd * 4];
                float lg = kr[0].x * qd.x + kr[1].x * qd.y + kr[2].x * qd.z + kr[3].x * qd.w;
                float ex = expf(lg * LOGIT_SCALE * cutS[es]);
                if ((kk & 3) == 0) atomicAdd(&g_den[ds * 4 + hd], ex);
                atomicAdd(&g_agg[ds * 16 + kk], ex * kvs[es][kk].y);
            }
        }
        __syncthreads();
    }
}

// ---------------- finalize per node (W_out, skip, FFN) + re-zero --------------
__global__ void k_final(const float* __restrict__ xf,
                        const float* __restrict__ Wout,
                        const float* __restrict__ Wf1,
                        const float* __restrict__ Wf2,
                        float* __restrict__ out) {
    __shared__ float Wo[256], F1[512], F2[512];
    int t = threadIdx.x;
    if (t < 256) Wo[t] = Wout[t];
    for (int i = t; i < 512; i += 256) { F1[i] = Wf1[i]; F2[i] = Wf2[i]; }
    __syncthreads();
    int n = blockIdx.x * 256 + t;
    if (n >= NN) return;

    float a[16];
#pragma unroll
    for (int k = 0; k < 16; k++) {
        float d = g_den[n * 4 + (k >> 2)];
        a[k] = (d > 0.0f) ? g_agg[n * 16 + k] / d : 0.0f;
        g_agg[n * 16 + k] = 0.0f;            // re-zero for next replay
    }
#pragma unroll
    for (int h = 0; h < 4; h++) g_den[n * 4 + h] = 0.0f;
    float attn[16];
#pragma unroll
    for (int k = 0; k < 16; k++) {
        float s = xf[n * 16 + k];
#pragma unroll
        for (int jj = 0; jj < 16; jj++) s += a[jj] * Wo[jj * 16 + k];
        attn[k] = s;
    }
    float na[32];
#pragma unroll
    for (int jj = 0; jj < 32; jj++) {
        float f = 0.0f;
#pragma unroll
        for (int i = 0; i < 16; i++) f += attn[i] * F1[i * 32 + jj];
        na[jj] = f * sigmoidf_(fabsf(f));
    }
#pragma unroll
    for (int k = 0; k < 16; k++) {
        float o = attn[k];
#pragma unroll
        for (int jj = 0; jj < 32; jj++) o += na[jj] * F2[jj * 16 + k];
        out[n * 16 + k] = o;
    }
}

// ---------------- launch ------------------------------------------------------
extern "C" void kernel_launch(void* const* d_in, const int* in_sizes, int n_in,
                              void* d_out, int out_size) {
    const float* xf   = (const float*)d_in[0];
    const float* sh   = (const float*)d_in[1];
    const float* emb  = (const float*)d_in[2];
    const float* elen = (const float*)d_in[3];
    const float* Wq   = (const float*)d_in[4];
    const float* kW1  = (const float*)d_in[5];
    const float* kb1  = (const float*)d_in[6];
    const float* kW2  = (const float*)d_in[7];
    const float* kb2  = (const float*)d_in[8];
    const float* vW1  = (const float*)d_in[9];
    const float* vb1  = (const float*)d_in[10];
    const float* vW2  = (const float*)d_in[11];
    const float* vb2  = (const float*)d_in[12];
    const float* Wdot = (const float*)d_in[13];
    const float* Wout = (const float*)d_in[14];
    const float* Wf1  = (const float*)d_in[15];
    const float* Wf2  = (const float*)d_in[16];
    const int*   eidx = (const int*)d_in[17];
    float* out = (float*)d_out;

    k_pro1<<<PRO1_TOTAL, 256>>>(eidx, kW2, vW2, xf, Wq, Wdot, kb2, vb2,
                                sh, emb, elen, kW1, kb1, vW1, vb1);
    k_pro2<<<1257, 512>>>(xf);
    k_scatter<<<(EE + 255) / 256, 256>>>(eidx);
    k_edges<<<NN, 256>>>();
    k_final<<<(NN + 255) / 256, 256>>>(xf, Wout, Wf1, Wf2, out);
}

// round 8
// speedup vs baseline: 1.6339x; 1.0988x over previous
#include <cuda_runtime.h>
#include <cuda_fp16.h>
#include <math.h>

#define NN 10000
#define EE 100000
#define TP_NORM 0.125f       // 1/sqrt(C*S)
#define LOGIT_SCALE 0.125f   // DOT_NORM * SCALE
#define INV_RADIUS 0.2f

typedef unsigned long long u64;
typedef unsigned int u32;

// ---------------- scratch ----------------------------------------------------
__device__ u32  g_QhK[(size_t)NN * 2048];   // half2 pairs (hid 2h,2h+1): [n][(s*16+k)*32 + h]
__device__ u32  g_QhV[(size_t)NN * 2048];
__device__ u64  g_Qbkv[NN * 64];            // (K,V) f32 pairs: [n][s*16+k]
__device__ u64  g_WtK[32768];               // W2 transposed: [(c*64+sk)*32 + h]
__device__ u64  g_WtV[32768];
__device__ u32  g_h1K[(size_t)EE * 32];     // half2 pairs, ORIGINAL edge order
__device__ u32  g_h1V[(size_t)EE * 32];
__device__ float2 g_dc[EE];                 // (dst bitcast, cutoff), original order
__device__ float4 g_sh4[EE];                // sh, original order
__device__ float g_qd[NN * 16];             // q @ W_dot
__device__ int   g_deg[NN];
__device__ int   g_rowptr[NN + 1];
__device__ int   g_cursor[NN];
__device__ int   g_eorder[EE];
__device__ float g_den[NN * 4];
__device__ float g_agg[NN * 16];

__device__ __forceinline__ float sigmoidf_(float x) { return 1.0f / (1.0f + expf(-x)); }
__device__ __forceinline__ u64 pk2(float lo, float hi) {
    u64 r; asm("mov.b64 %0, {%1, %2};" : "=l"(r) : "f"(lo), "f"(hi)); return r;
}
__device__ __forceinline__ float2 up2(u64 v) {
    float2 f; asm("mov.b64 {%0, %1}, %2;" : "=f"(f.x), "=f"(f.y) : "l"(v)); return f;
}
__device__ __forceinline__ u64 dup2(float x) { return pk2(x, x); }
__device__ __forceinline__ u64 fma2_(u64 a, u64 b, u64 c) {
    u64 d; asm("fma.rn.f32x2 %0, %1, %2, %3;" : "=l"(d) : "l"(a), "l"(b), "l"(c)); return d;
}
__device__ __forceinline__ u32 pack_h2(float lo, float hi) {
    __half2 h = __floats2half2_rn(lo, hi);
    return *reinterpret_cast<u32*>(&h);
}
__device__ __forceinline__ u64 unpack_h2(u32 v) {
    __half2 h = *reinterpret_cast<__half2*>(&v);
    float2 f = __half22float2(h);
    return pk2(f.x, f.y);
}

// ================= PRO1: fused independent prologue (256-thread blocks) ======
// block ranges: [0,391) hist | [391,647) transW | [647,1272) qprojd | [1272,7522) mlp
#define PRO1_HIST   391
#define PRO1_TRANSW (PRO1_HIST + 256)
#define PRO1_QPROJD (PRO1_TRANSW + 625)
#define PRO1_TOTAL  (PRO1_QPROJD + 6250)

__global__ void __launch_bounds__(256) k_pro1(
    const int* __restrict__ eidx,
    const float* __restrict__ kW2, const float* __restrict__ vW2,
    const float* __restrict__ xf,  const float* __restrict__ Wq,
    const float* __restrict__ Wdot,
    const float* __restrict__ kb2, const float* __restrict__ vb2,
    const float* __restrict__ sh,  const float* __restrict__ emb,
    const float* __restrict__ elen,
    const float* __restrict__ kW1, const float* __restrict__ kb1,
    const float* __restrict__ vW1, const float* __restrict__ vb1) {

    int blk = blockIdx.x;
    int t = threadIdx.x;

    if (blk < PRO1_HIST) {
        int e = blk * 256 + t;
        if (e < EE) atomicAdd(&g_deg[eidx[e]], 1);

    } else if (blk < PRO1_TRANSW) {
        int b = blk - PRO1_HIST;
        int tz = b >> 7;
        int i = (b & 127) * 256 + t;
        const float* W = tz ? vW2 : kW2;
        u64* out = tz ? g_WtV : g_WtK;
        int h = i & 31, csk = i >> 5;
        out[i] = pk2(W[(2 * h) * 1024 + csk], W[(2 * h + 1) * 1024 + csk]);

    } else if (blk < PRO1_QPROJD) {
        __shared__ float Wqs[256], Wds[16], Xs[16][16], B2K[1024], B2V[1024];
        if (t < 256) Wqs[t] = Wq[t];
        if (t < 16)  Wds[t] = Wdot[t];
        for (int i = t; i < 1024; i += 256) { B2K[i] = kb2[i]; B2V[i] = vb2[i]; }
        int n0 = (blk - PRO1_TRANSW) * 16;
        { int nl = t >> 4, c = t & 15; Xs[nl][c] = xf[(n0 + nl) * 16 + c]; }
        __syncthreads();
        int nl = t >> 4, k = t & 15;
        int n = n0 + nl;
        int head = k >> 2, j = k & 3;
        float qd = 0.0f;
#pragma unroll
        for (int i2 = 0; i2 < 4; i2++) {
            float q = 0.0f;
#pragma unroll
            for (int c = 0; c < 16; c++) q += Xs[nl][c] * Wqs[c * 16 + head * 4 + i2];
            qd += q * Wds[i2 * 4 + j];
        }
        g_qd[n * 16 + k] = qd;
#pragma unroll
        for (int s = 0; s < 4; s++) {
            float aK = 0.0f, aV = 0.0f;
#pragma unroll
            for (int c = 0; c < 16; c++) {
                float x = Xs[nl][c];
                aK += x * B2K[c * 64 + s * 16 + k];
                aV += x * B2V[c * 64 + s * 16 + k];
            }
            g_Qbkv[n * 64 + s * 16 + k] = pk2(aK, aV);
        }

    } else {
        __shared__ float emb_s[16][16];
        int e0 = (blk - PRO1_QPROJD) * 16;
        { int el = t >> 4, b = t & 15; emb_s[el][b] = emb[(e0 + el) * 16 + b]; }
        if (t < 16) {
            int e = e0 + t;
            int ds = eidx[EE + e];
            float cut = sigmoidf_(10.0f * (1.0f - elen[e] * INV_RADIUS));
            g_dc[e] = make_float2(__int_as_float(ds), cut);
            g_sh4[e] = *reinterpret_cast<const float4*>(sh + e * 4);
        }
        __syncthreads();
        int h = t & 31, tz = (t >> 5) & 1, elg = t >> 6;
        const u64* __restrict__ W1 = reinterpret_cast<const u64*>(tz ? vW1 : kW1);
        const u64* __restrict__ b1 = reinterpret_cast<const u64*>(tz ? vb1 : kb1);
        u32* __restrict__ H = tz ? g_h1V : g_h1K;
        u64 w1r[16];
#pragma unroll
        for (int b = 0; b < 16; b++) w1r[b] = __ldg(&W1[b * 32 + h]);
        u64 bb = __ldg(&b1[h]);
#pragma unroll
        for (int r = 0; r < 4; r++) {
            int el = r * 4 + elg;
            u64 acc = bb;
#pragma unroll
            for (int b = 0; b < 16; b++) acc = fma2_(dup2(emb_s[el][b]), w1r[b], acc);
            float2 f = up2(acc);
            f.x = f.x * sigmoidf_(f.x);
            f.y = f.y * sigmoidf_(f.y);
            H[(size_t)(e0 + el) * 32 + h] = pack_h2(f.x, f.y);
        }
    }
}

// ================= PRO2: scan (block 0) + qweights (blocks 1..1256) ==========
__global__ void __launch_bounds__(512) k_pro2(const float* __restrict__ xf) {
    int blk = blockIdx.x;
    int t = threadIdx.x;

    if (blk == 0) {
        __shared__ int ps[512];
        const int PER = 20;
        int start = t * PER;
        int sum = 0;
        int local[PER];
        for (int i = 0; i < PER; i++) {
            int idx = start + i;
            local[i] = (idx < NN) ? g_deg[idx] : 0;
            if (idx < NN) g_deg[idx] = 0;
            sum += local[i];
        }
        ps[t] = sum;
        __syncthreads();
        for (int off = 1; off < 512; off <<= 1) {
            int add = (t >= off) ? ps[t - off] : 0;
            __syncthreads();
            ps[t] += add;
            __syncthreads();
        }
        int base = ps[t] - sum;
        for (int i = 0; i < PER; i++) {
            int idx = start + i;
            if (idx < NN) { g_rowptr[idx] = base; g_cursor[idx] = base; base += local[i]; }
        }
        if (t == 511) g_rowptr[NN] = ps[511];

    } else {
        int b = blk - 1;
        int n0 = (b % 157) * 64;
        int h8 = ((b / 157) & 3) * 8;
        int tz = b / 628;
        __shared__ u64 Xd[64 * 16];
        for (int i = t; i < 1024; i += 512) {
            int n = n0 + (i >> 4);
            Xd[i] = dup2((n < NN) ? xf[n * 16 + (i & 15)] : 0.0f);
        }
        __syncthreads();
        int hp = t & 7, sk = t >> 3;
        const u64* __restrict__ Wt = tz ? g_WtV : g_WtK;
        u32* __restrict__ Qh = tz ? g_QhV : g_QhK;
        u64 wreg[16];
#pragma unroll
        for (int c = 0; c < 16; c++) wreg[c] = __ldg(&Wt[(c * 64 + sk) * 32 + h8 + hp]);
#pragma unroll 4
        for (int n = 0; n < 64; n++) {
            u64 acc = 0ULL;
#pragma unroll
            for (int c = 0; c < 16; c++) acc = fma2_(Xd[n * 16 + c], wreg[c], acc);
            if (n0 + n < NN) {
                float2 f = up2(acc);
                Qh[(size_t)(n0 + n) * 2048 + sk * 32 + h8 + hp] = pack_h2(f.x, f.y);
            }
        }
    }
}

// ---------------- scatter edges grouped by src --------------------------------
__global__ void k_scatter(const int* __restrict__ eidx) {
    int e = blockIdx.x * 256 + threadIdx.x;
    if (e < EE) {
        int s = eidx[e];
        int pos = atomicAdd(&g_cursor[s], 1);
        g_eorder[pos] = e;
    }
}

// ---------------- main edge contraction (one block per source node) -----------
// 256 threads: k = t>>4 (channel), g = t&15 (hid-pair slice, pair h = i*16+g).
// 16-edge tiles: one stage/compute/epilogue round for typical (deg<=16) nodes.
__global__ void __launch_bounds__(256) k_edges() {
    __shared__ int    dstS[16];
    __shared__ float  cutS[16];
    __shared__ float4 shS[16];
    __shared__ u32    h1Ks[16][32];
    __shared__ u32    h1Vs[16][32];
    __shared__ float2 kvs[16][16];

    int node = blockIdx.x;
    int t = threadIdx.x;
    int k = t >> 4, g = t & 15;

    // issue per-node Q loads early (overlaps rowptr load latency)
    const u32* __restrict__ QK = g_QhK + (size_t)node * 2048;
    const u32* __restrict__ QV = g_QhV + (size_t)node * 2048;
    u32 rqK[2][4], rqV[2][4];
#pragma unroll
    for (int i = 0; i < 2; i++)
#pragma unroll
        for (int s = 0; s < 4; s++) {
            int idx = (s * 16 + k) * 32 + i * 16 + g;
            rqK[i][s] = __ldg(&QK[idx]);
            rqV[i][s] = __ldg(&QV[idx]);
        }

    int r0 = g_rowptr[node], deg = g_rowptr[node + 1] - r0;
    if (deg == 0) return;

    u64 qK[2][4], qV[2][4];
#pragma unroll
    for (int i = 0; i < 2; i++)
#pragma unroll
        for (int s = 0; s < 4; s++) {
            qK[i][s] = unpack_h2(rqK[i][s]);
            qV[i][s] = unpack_h2(rqV[i][s]);
        }
    u64 qb[4];
    if (g == 0) {
#pragma unroll
        for (int s = 0; s < 4; s++) qb[s] = g_Qbkv[node * 64 + s * 16 + k];
    }

    for (int base = 0; base < deg; base += 16) {
        int nval = min(16, deg - base);
        // ---- staging: h1 tiles (2 rounds of 8 es) + per-edge meta ----
        {
            int esw = t >> 5, h = t & 31;
#pragma unroll
            for (int r = 0; r < 2; r++) {
                int es = r * 8 + esw;
                if (es < nval) {
                    int e = __ldg(&g_eorder[r0 + base + es]);
                    h1Ks[es][h] = __ldg(&g_h1K[(size_t)e * 32 + h]);
                    h1Vs[es][h] = __ldg(&g_h1V[(size_t)e * 32 + h]);
                }
            }
            if (t < 16) {
                if (t < nval) {
                    int e2 = __ldg(&g_eorder[r0 + base + t]);
                    float2 dc = g_dc[e2];
                    dstS[t] = __float_as_int(dc.x);
                    cutS[t] = dc.y;
                    shS[t]  = g_sh4[e2];
                } else {
                    dstS[t] = -1;
                }
            }
        }
        __syncthreads();

        // ---- compute: runtime-bounded loop over live edge slots ----
#pragma unroll 4
        for (int es = 0; es < nval; es++) {
            float4 s4 = shS[es];
            u64 sh0 = dup2(s4.x), sh1 = dup2(s4.y), sh2 = dup2(s4.z), sh3 = dup2(s4.w);
            u64 accK = 0ULL, accV = 0ULL;
#pragma unroll
            for (int i = 0; i < 2; i++) {
                u64 ddK = fma2_(sh0, qK[i][0], 0ULL);
                ddK = fma2_(sh1, qK[i][1], ddK);
                ddK = fma2_(sh2, qK[i][2], ddK);
                ddK = fma2_(sh3, qK[i][3], ddK);
                u64 ddV = fma2_(sh0, qV[i][0], 0ULL);
                ddV = fma2_(sh1, qV[i][1], ddV);
                ddV = fma2_(sh2, qV[i][2], ddV);
                ddV = fma2_(sh3, qV[i][3], ddV);
                u64 hK = unpack_h2(h1Ks[es][i * 16 + g]);
                u64 hV = unpack_h2(h1Vs[es][i * 16 + g]);
                accK = fma2_(hK, ddK, accK);
                accV = fma2_(hV, ddV, accV);
            }
            float2 aK = up2(accK), aV = up2(accV);
            float kv_k = aK.x + aK.y;
            float kv_v = aV.x + aV.y;
            kv_k += __shfl_xor_sync(0xffffffffu, kv_k, 1);
            kv_v += __shfl_xor_sync(0xffffffffu, kv_v, 1);
            kv_k += __shfl_xor_sync(0xffffffffu, kv_k, 2);
            kv_v += __shfl_xor_sync(0xffffffffu, kv_v, 2);
            kv_k += __shfl_xor_sync(0xffffffffu, kv_k, 4);
            kv_v += __shfl_xor_sync(0xffffffffu, kv_v, 4);
            kv_k += __shfl_xor_sync(0xffffffffu, kv_k, 8);
            kv_v += __shfl_xor_sync(0xffffffffu, kv_v, 8);
            if (g == 0) {
                u64 bacc = fma2_(sh0, qb[0], 0ULL);
                bacc = fma2_(sh1, qb[1], bacc);
                bacc = fma2_(sh2, qb[2], bacc);
                bacc = fma2_(sh3, qb[3], bacc);
                float2 bb = up2(bacc);
                kvs[es][k] = make_float2((kv_k + bb.x) * TP_NORM, (kv_v + bb.y) * TP_NORM);
            }
        }
        __syncthreads();

        // ---- epilogue: all 256 threads, one atomic each (16 es x 16 kk) ----
        {
            int es = t >> 4, kk = t & 15, hd = kk >> 2;
            int ds = dstS[es];
            if (ds >= 0) {
                float4 qd = *reinterpret_cast<const float4*>(g_qd + ds * 16 + hd * 4);
                const float2* kr = &kvs[es][hd * 4];
                float lg = kr[0].x * qd.x + kr[1].x * qd.y + kr[2].x * qd.z + kr[3].x * qd.w;
                float ex = expf(lg * LOGIT_SCALE * cutS[es]);
                if ((kk & 3) == 0) atomicAdd(&g_den[ds * 4 + hd], ex);
                atomicAdd(&g_agg[ds * 16 + kk], ex * kvs[es][kk].y);
            }
        }
        __syncthreads();
    }
}

// ---------------- finalize per node (W_out, skip, FFN) + re-zero --------------
__global__ void k_final(const float* __restrict__ xf,
                        const float* __restrict__ Wout,
                        const float* __restrict__ Wf1,
                        const float* __restrict__ Wf2,
                        float* __restrict__ out) {
    __shared__ float Wo[256], F1[512], F2[512];
    int t = threadIdx.x;
    if (t < 256) Wo[t] = Wout[t];
    for (int i = t; i < 512; i += 256) { F1[i] = Wf1[i]; F2[i] = Wf2[i]; }
    __syncthreads();
    int n = blockIdx.x * 256 + t;
    if (n >= NN) return;

    float a[16];
#pragma unroll
    for (int k = 0; k < 16; k++) {
        float d = g_den[n * 4 + (k >> 2)];
        a[k] = (d > 0.0f) ? g_agg[n * 16 + k] / d : 0.0f;
        g_agg[n * 16 + k] = 0.0f;            // re-zero for next replay
    }
#pragma unroll
    for (int h = 0; h < 4; h++) g_den[n * 4 + h] = 0.0f;
    float attn[16];
#pragma unroll
    for (int k = 0; k < 16; k++) {
        float s = xf[n * 16 + k];
#pragma unroll
        for (int jj = 0; jj < 16; jj++) s += a[jj] * Wo[jj * 16 + k];
        attn[k] = s;
    }
    float na[32];
#pragma unroll
    for (int jj = 0; jj < 32; jj++) {
        float f = 0.0f;
#pragma unroll
        for (int i = 0; i < 16; i++) f += attn[i] * F1[i * 32 + jj];
        na[jj] = f * sigmoidf_(fabsf(f));
    }
#pragma unroll
    for (int k = 0; k < 16; k++) {
        float o = attn[k];
#pragma unroll
        for (int jj = 0; jj < 32; jj++) o += na[jj] * F2[jj * 16 + k];
        out[n * 16 + k] = o;
    }
}

// ---------------- launch ------------------------------------------------------
extern "C" void kernel_launch(void* const* d_in, const int* in_sizes, int n_in,
                              void* d_out, int out_size) {
    const float* xf   = (const float*)d_in[0];
    const float* sh   = (const float*)d_in[1];
    const float* emb  = (const float*)d_in[2];
    const float* elen = (const float*)d_in[3];
    const float* Wq   = (const float*)d_in[4];
    const float* kW1  = (const float*)d_in[5];
    const float* kb1  = (const float*)d_in[6];
    const float* kW2  = (const float*)d_in[7];
    const float* kb2  = (const float*)d_in[8];
    const float* vW1  = (const float*)d_in[9];
    const float* vb1  = (const float*)d_in[10];
    const float* vW2  = (const float*)d_in[11];
    const float* vb2  = (const float*)d_in[12];
    const float* Wdot = (const float*)d_in[13];
    const float* Wout = (const float*)d_in[14];
    const float* Wf1  = (const float*)d_in[15];
    const float* Wf2  = (const float*)d_in[16];
    const int*   eidx = (const int*)d_in[17];
    float* out = (float*)d_out;

    k_pro1<<<PRO1_TOTAL, 256>>>(eidx, kW2, vW2, xf, Wq, Wdot, kb2, vb2,
                                sh, emb, elen, kW1, kb1, vW1, vb1);
    k_pro2<<<1257, 512>>>(xf);
    k_scatter<<<(EE + 255) / 256, 256>>>(eidx);
    k_edges<<<NN, 256>>>();
    k_final<<<(NN + 255) / 256, 256>>>(xf, Wout, Wf1, Wf2, out);
}

// round 10
// speedup vs baseline: 1.7673x; 1.0817x over previous
#include <cuda_runtime.h>
#include <cuda_fp16.h>
#include <math.h>

#define NN 10000
#define EE 100000
#define TP_NORM 0.125f       // 1/sqrt(C*S)
#define LOGIT_SCALE 0.125f   // DOT_NORM * SCALE
#define INV_RADIUS 0.2f

typedef unsigned long long u64;
typedef unsigned int u32;

// ---------------- scratch ----------------------------------------------------
__device__ u32  g_QhK[(size_t)NN * 2048];   // half2 pairs (hid 2h,2h+1): [n][(s*16+k)*32 + h]
__device__ u32  g_QhV[(size_t)NN * 2048];
__device__ u64  g_Qbkv[NN * 64];            // (K,V) f32 pairs: [n][s*16+k]
__device__ u64  g_WtK[32768];               // W2 transposed: [(c*64+sk)*32 + h]
__device__ u64  g_WtV[32768];
__device__ u32  g_h1K[(size_t)EE * 32];     // half2 pairs, ORIGINAL edge order
__device__ u32  g_h1V[(size_t)EE * 32];
__device__ float2 g_dc[EE];                 // (dst bitcast, cutoff), original order
__device__ float4 g_sh4[EE];                // sh, original order
__device__ float g_qd[NN * 16];             // q @ W_dot
__device__ int   g_deg[NN];
__device__ int   g_rowptr[NN + 1];
__device__ int   g_cursor[NN];
__device__ int   g_eorder[EE];
__device__ float g_den[NN * 4];
__device__ float g_agg[NN * 16];

__device__ __forceinline__ float sigmoidf_(float x) { return 1.0f / (1.0f + expf(-x)); }
__device__ __forceinline__ u64 pk2(float lo, float hi) {
    u64 r; asm("mov.b64 %0, {%1, %2};" : "=l"(r) : "f"(lo), "f"(hi)); return r;
}
__device__ __forceinline__ float2 up2(u64 v) {
    float2 f; asm("mov.b64 {%0, %1}, %2;" : "=f"(f.x), "=f"(f.y) : "l"(v)); return f;
}
__device__ __forceinline__ u64 dup2(float x) { return pk2(x, x); }
__device__ __forceinline__ u64 fma2_(u64 a, u64 b, u64 c) {
    u64 d; asm("fma.rn.f32x2 %0, %1, %2, %3;" : "=l"(d) : "l"(a), "l"(b), "l"(c)); return d;
}
__device__ __forceinline__ u32 pack_h2(float lo, float hi) {
    __half2 h = __floats2half2_rn(lo, hi);
    return *reinterpret_cast<u32*>(&h);
}
__device__ __forceinline__ u64 unpack_h2(u32 v) {
    __half2 h = *reinterpret_cast<__half2*>(&v);
    float2 f = __half22float2(h);
    return pk2(f.x, f.y);
}
__device__ __forceinline__ __half2 as_h2(u32 v) { return *reinterpret_cast<__half2*>(&v); }
__device__ __forceinline__ u32 h2_as_u32(__half2 h) { return *reinterpret_cast<u32*>(&h); }

// ================= PRO1: fused independent prologue (256-thread blocks) ======
// block ranges: [0,391) hist | [391,647) transW | [647,1272) qprojd | [1272,7522) mlp
#define PRO1_HIST   391
#define PRO1_TRANSW (PRO1_HIST + 256)
#define PRO1_QPROJD (PRO1_TRANSW + 625)
#define PRO1_TOTAL  (PRO1_QPROJD + 6250)

__global__ void __launch_bounds__(256) k_pro1(
    const int* __restrict__ eidx,
    const float* __restrict__ kW2, const float* __restrict__ vW2,
    const float* __restrict__ xf,  const float* __restrict__ Wq,
    const float* __restrict__ Wdot,
    const float* __restrict__ kb2, const float* __restrict__ vb2,
    const float* __restrict__ sh,  const float* __restrict__ emb,
    const float* __restrict__ elen,
    const float* __restrict__ kW1, const float* __restrict__ kb1,
    const float* __restrict__ vW1, const float* __restrict__ vb1) {

    int blk = blockIdx.x;
    int t = threadIdx.x;

    if (blk < PRO1_HIST) {
        int e = blk * 256 + t;
        if (e < EE) atomicAdd(&g_deg[eidx[e]], 1);

    } else if (blk < PRO1_TRANSW) {
        int b = blk - PRO1_HIST;
        int tz = b >> 7;
        int i = (b & 127) * 256 + t;
        const float* W = tz ? vW2 : kW2;
        u64* out = tz ? g_WtV : g_WtK;
        int h = i & 31, csk = i >> 5;
        out[i] = pk2(W[(2 * h) * 1024 + csk], W[(2 * h + 1) * 1024 + csk]);

    } else if (blk < PRO1_QPROJD) {
        __shared__ float Wqs[256], Wds[16], Xs[16][16], B2K[1024], B2V[1024];
        if (t < 256) Wqs[t] = Wq[t];
        if (t < 16)  Wds[t] = Wdot[t];
        for (int i = t; i < 1024; i += 256) { B2K[i] = kb2[i]; B2V[i] = vb2[i]; }
        int n0 = (blk - PRO1_TRANSW) * 16;
        { int nl = t >> 4, c = t & 15; Xs[nl][c] = xf[(n0 + nl) * 16 + c]; }
        __syncthreads();
        int nl = t >> 4, k = t & 15;
        int n = n0 + nl;
        int head = k >> 2, j = k & 3;
        float qd = 0.0f;
#pragma unroll
        for (int i2 = 0; i2 < 4; i2++) {
            float q = 0.0f;
#pragma unroll
            for (int c = 0; c < 16; c++) q += Xs[nl][c] * Wqs[c * 16 + head * 4 + i2];
            qd += q * Wds[i2 * 4 + j];
        }
        g_qd[n * 16 + k] = qd;
#pragma unroll
        for (int s = 0; s < 4; s++) {
            float aK = 0.0f, aV = 0.0f;
#pragma unroll
            for (int c = 0; c < 16; c++) {
                float x = Xs[nl][c];
                aK += x * B2K[c * 64 + s * 16 + k];
                aV += x * B2V[c * 64 + s * 16 + k];
            }
            g_Qbkv[n * 64 + s * 16 + k] = pk2(aK, aV);
        }

    } else {
        __shared__ float emb_s[16][16];
        int e0 = (blk - PRO1_QPROJD) * 16;
        { int el = t >> 4, b = t & 15; emb_s[el][b] = emb[(e0 + el) * 16 + b]; }
        if (t < 16) {
            int e = e0 + t;
            int ds = eidx[EE + e];
            float cut = sigmoidf_(10.0f * (1.0f - elen[e] * INV_RADIUS));
            g_dc[e] = make_float2(__int_as_float(ds), cut);
            g_sh4[e] = *reinterpret_cast<const float4*>(sh + e * 4);
        }
        __syncthreads();
        int h = t & 31, tz = (t >> 5) & 1, elg = t >> 6;
        const u64* __restrict__ W1 = reinterpret_cast<const u64*>(tz ? vW1 : kW1);
        const u64* __restrict__ b1 = reinterpret_cast<const u64*>(tz ? vb1 : kb1);
        u32* __restrict__ H = tz ? g_h1V : g_h1K;
        u64 w1r[16];
#pragma unroll
        for (int b = 0; b < 16; b++) w1r[b] = __ldg(&W1[b * 32 + h]);
        u64 bb = __ldg(&b1[h]);
#pragma unroll
        for (int r = 0; r < 4; r++) {
            int el = r * 4 + elg;
            u64 acc = bb;
#pragma unroll
            for (int b = 0; b < 16; b++) acc = fma2_(dup2(emb_s[el][b]), w1r[b], acc);
            float2 f = up2(acc);
            f.x = f.x * sigmoidf_(f.x);
            f.y = f.y * sigmoidf_(f.y);
            H[(size_t)(e0 + el) * 32 + h] = pack_h2(f.x, f.y);
        }
    }
}

// ================= PRO2: scan (block 0) + qweights (blocks 1..1256) ==========
__global__ void __launch_bounds__(512) k_pro2(const float* __restrict__ xf) {
    int blk = blockIdx.x;
    int t = threadIdx.x;

    if (blk == 0) {
        __shared__ int ps[512];
        const int PER = 20;
        int start = t * PER;
        int sum = 0;
        int local[PER];
        for (int i = 0; i < PER; i++) {
            int idx = start + i;
            local[i] = (idx < NN) ? g_deg[idx] : 0;
            if (idx < NN) g_deg[idx] = 0;
            sum += local[i];
        }
        ps[t] = sum;
        __syncthreads();
        for (int off = 1; off < 512; off <<= 1) {
            int add = (t >= off) ? ps[t - off] : 0;
            __syncthreads();
            ps[t] += add;
            __syncthreads();
        }
        int base = ps[t] - sum;
        for (int i = 0; i < PER; i++) {
            int idx = start + i;
            if (idx < NN) { g_rowptr[idx] = base; g_cursor[idx] = base; base += local[i]; }
        }
        if (t == 511) g_rowptr[NN] = ps[511];

    } else {
        int b = blk - 1;
        int n0 = (b % 157) * 64;
        int h8 = ((b / 157) & 3) * 8;
        int tz = b / 628;
        __shared__ u64 Xd[64 * 16];
        for (int i = t; i < 1024; i += 512) {
            int n = n0 + (i >> 4);
            Xd[i] = dup2((n < NN) ? xf[n * 16 + (i & 15)] : 0.0f);
        }
        __syncthreads();
        int hp = t & 7, sk = t >> 3;
        const u64* __restrict__ Wt = tz ? g_WtV : g_WtK;
        u32* __restrict__ Qh = tz ? g_QhV : g_QhK;
        u64 wreg[16];
#pragma unroll
        for (int c = 0; c < 16; c++) wreg[c] = __ldg(&Wt[(c * 64 + sk) * 32 + h8 + hp]);
#pragma unroll 4
        for (int n = 0; n < 64; n++) {
            u64 acc = 0ULL;
#pragma unroll
            for (int c = 0; c < 16; c++) acc = fma2_(Xd[n * 16 + c], wreg[c], acc);
            if (n0 + n < NN) {
                float2 f = up2(acc);
                Qh[(size_t)(n0 + n) * 2048 + sk * 32 + h8 + hp] = pack_h2(f.x, f.y);
            }
        }
    }
}

// ---------------- scatter edges grouped by src --------------------------------
__global__ void k_scatter(const int* __restrict__ eidx) {
    int e = blockIdx.x * 256 + threadIdx.x;
    if (e < EE) {
        int s = eidx[e];
        int pos = atomicAdd(&g_cursor[s], 1);
        g_eorder[pos] = e;
    }
}

// ---------------- main edge contraction (one block per source node) -----------
// 256 threads: k = t>>4 (channel), g = t&15 (hid-pair slice, pair h = i*16+g).
// Q held as raw half2 (16 u32 regs); dd computed in HFMA2; forced 4 blocks/SM.
__global__ void __launch_bounds__(256, 4) k_edges() {
    __shared__ int    dstS[16];
    __shared__ float  cutS[16];
    __shared__ float4 shS[16];
    __shared__ u32    sh2S[16][4];      // duplicated-half2 sh per edge slot
    __shared__ u32    h1Ks[16][32];
    __shared__ u32    h1Vs[16][32];
    __shared__ float2 kvs[16][16];

    int node = blockIdx.x;
    int t = threadIdx.x;
    int k = t >> 4, g = t & 15;

    // per-node Q slice, kept packed as half2 (16+16 u32 registers)
    const u32* __restrict__ QK = g_QhK + (size_t)node * 2048;
    const u32* __restrict__ QV = g_QhV + (size_t)node * 2048;
    u32 qK[2][4], qV[2][4];
#pragma unroll
    for (int i = 0; i < 2; i++)
#pragma unroll
        for (int s = 0; s < 4; s++) {
            int idx = (s * 16 + k) * 32 + i * 16 + g;
            qK[i][s] = __ldg(&QK[idx]);
            qV[i][s] = __ldg(&QV[idx]);
        }

    int r0 = g_rowptr[node], deg = g_rowptr[node + 1] - r0;
    if (deg == 0) return;

    u64 qb[4];
    if (g == 0) {
#pragma unroll
        for (int s = 0; s < 4; s++) qb[s] = g_Qbkv[node * 64 + s * 16 + k];
    }

    for (int base = 0; base < deg; base += 16) {
        int nval = min(16, deg - base);
        // ---- staging: h1 tiles (2 rounds of 8 es) + per-edge meta ----
        {
            int esw = t >> 5, h = t & 31;
#pragma unroll
            for (int r = 0; r < 2; r++) {
                int es = r * 8 + esw;
                if (es < nval) {
                    int e = __ldg(&g_eorder[r0 + base + es]);
                    h1Ks[es][h] = __ldg(&g_h1K[(size_t)e * 32 + h]);
                    h1Vs[es][h] = __ldg(&g_h1V[(size_t)e * 32 + h]);
                }
            }
            if (t < 16) {
                if (t < nval) {
                    int e2 = __ldg(&g_eorder[r0 + base + t]);
                    float2 dc = g_dc[e2];
                    dstS[t] = __float_as_int(dc.x);
                    cutS[t] = dc.y;
                    float4 s4 = g_sh4[e2];
                    shS[t] = s4;
                    sh2S[t][0] = h2_as_u32(__float2half2_rn(s4.x));
                    sh2S[t][1] = h2_as_u32(__float2half2_rn(s4.y));
                    sh2S[t][2] = h2_as_u32(__float2half2_rn(s4.z));
                    sh2S[t][3] = h2_as_u32(__float2half2_rn(s4.w));
                } else {
                    dstS[t] = -1;
                }
            }
        }
        __syncthreads();

        // ---- compute: runtime-bounded loop over live edge slots ----
#pragma unroll 4
        for (int es = 0; es < nval; es++) {
            __half2 s0 = as_h2(sh2S[es][0]);
            __half2 s1 = as_h2(sh2S[es][1]);
            __half2 s2 = as_h2(sh2S[es][2]);
            __half2 s3 = as_h2(sh2S[es][3]);
            u64 accK = 0ULL, accV = 0ULL;
#pragma unroll
            for (int i = 0; i < 2; i++) {
                __half2 dK = __hmul2(s0, as_h2(qK[i][0]));
                dK = __hfma2(s1, as_h2(qK[i][1]), dK);
                dK = __hfma2(s2, as_h2(qK[i][2]), dK);
                dK = __hfma2(s3, as_h2(qK[i][3]), dK);
                __half2 dV = __hmul2(s0, as_h2(qV[i][0]));
                dV = __hfma2(s1, as_h2(qV[i][1]), dV);
                dV = __hfma2(s2, as_h2(qV[i][2]), dV);
                dV = __hfma2(s3, as_h2(qV[i][3]), dV);
                float2 dKf = __half22float2(dK);
                float2 dVf = __half22float2(dV);
                u64 hK = unpack_h2(h1Ks[es][i * 16 + g]);
                u64 hV = unpack_h2(h1Vs[es][i * 16 + g]);
                accK = fma2_(hK, pk2(dKf.x, dKf.y), accK);
                accV = fma2_(hV, pk2(dVf.x, dVf.y), accV);
            }
            float2 aK = up2(accK), aV = up2(accV);
            float kv_k = aK.x + aK.y;
            float kv_v = aV.x + aV.y;
            kv_k += __shfl_xor_sync(0xffffffffu, kv_k, 1);
            kv_v += __shfl_xor_sync(0xffffffffu, kv_v, 1);
            kv_k += __shfl_xor_sync(0xffffffffu, kv_k, 2);
            kv_v += __shfl_xor_sync(0xffffffffu, kv_v, 2);
            kv_k += __shfl_xor_sync(0xffffffffu, kv_k, 4);
            kv_v += __shfl_xor_sync(0xffffffffu, kv_v, 4);
            kv_k += __shfl_xor_sync(0xffffffffu, kv_k, 8);
            kv_v += __shfl_xor_sync(0xffffffffu, kv_v, 8);
            if (g == 0) {
                float4 s4 = shS[es];
                u64 bacc = fma2_(dup2(s4.x), qb[0], 0ULL);
                bacc = fma2_(dup2(s4.y), qb[1], bacc);
                bacc = fma2_(dup2(s4.z), qb[2], bacc);
                bacc = fma2_(dup2(s4.w), qb[3], bacc);
                float2 bb = up2(bacc);
                kvs[es][k] = make_float2((kv_k + bb.x) * TP_NORM, (kv_v + bb.y) * TP_NORM);
            }
        }
        __syncthreads();

        // ---- epilogue: all 256 threads, one atomic each (16 es x 16 kk) ----
        {
            int es = t >> 4, kk = t & 15, hd = kk >> 2;
            int ds = dstS[es];
            if (ds >= 0) {
                float4 qd = *reinterpret_cast<const float4*>(g_qd + ds * 16 + hd * 4);
                const float2* kr = &kvs[es][hd * 4];
                float lg = kr[0].x * qd.x + kr[1].x * qd.y + kr[2].x * qd.z + kr[3].x * qd.w;
                float ex = expf(lg * LOGIT_SCALE * cutS[es]);
                if ((kk & 3) == 0) atomicAdd(&g_den[ds * 4 + hd], ex);
                atomicAdd(&g_agg[ds * 16 + kk], ex * kvs[es][kk].y);
            }
        }
        __syncthreads();
    }
}

// ---------------- finalize per node (W_out, skip, FFN) + re-zero --------------
__global__ void k_final(const float* __restrict__ xf,
                        const float* __restrict__ Wout,
                        const float* __restrict__ Wf1,
                        const float* __restrict__ Wf2,
                        float* __restrict__ out) {
    __shared__ float Wo[256], F1[512], F2[512];
    int t = threadIdx.x;
    if (t < 256) Wo[t] = Wout[t];
    for (int i = t; i < 512; i += 256) { F1[i] = Wf1[i]; F2[i] = Wf2[i]; }
    __syncthreads();
    int n = blockIdx.x * 256 + t;
    if (n >= NN) return;

    float a[16];
#pragma unroll
    for (int k = 0; k < 16; k++) {
        float d = g_den[n * 4 + (k >> 2)];
        a[k] = (d > 0.0f) ? g_agg[n * 16 + k] / d : 0.0f;
        g_agg[n * 16 + k] = 0.0f;            // re-zero for next replay
    }
#pragma unroll
    for (int h = 0; h < 4; h++) g_den[n * 4 + h] = 0.0f;
    float attn[16];
#pragma unroll
    for (int k = 0; k < 16; k++) {
        float s = xf[n * 16 + k];
#pragma unroll
        for (int jj = 0; jj < 16; jj++) s += a[jj] * Wo[jj * 16 + k];
        attn[k] = s;
    }
    float na[32];
#pragma unroll
    for (int jj = 0; jj < 32; jj++) {
        float f = 0.0f;
#pragma unroll
        for (int i = 0; i < 16; i++) f += attn[i] * F1[i * 32 + jj];
        na[jj] = f * sigmoidf_(fabsf(f));
    }
#pragma unroll
    for (int k = 0; k < 16; k++) {
        float o = attn[k];
#pragma unroll
        for (int jj = 0; jj < 32; jj++) o += na[jj] * F2[jj * 16 + k];
        out[n * 16 + k] = o;
    }
}

// ---------------- launch ------------------------------------------------------
extern "C" void kernel_launch(void* const* d_in, const int* in_sizes, int n_in,
                              void* d_out, int out_size) {
    const float* xf   = (const float*)d_in[0];
    const float* sh   = (const float*)d_in[1];
    const float* emb  = (const float*)d_in[2];
    const float* elen = (const float*)d_in[3];
    const float* Wq   = (const float*)d_in[4];
    const float* kW1  = (const float*)d_in[5];
    const float* kb1  = (const float*)d_in[6];
    const float* kW2  = (const float*)d_in[7];
    const float* kb2  = (const float*)d_in[8];
    const float* vW1  = (const float*)d_in[9];
    const float* vb1  = (const float*)d_in[10];
    const float* vW2  = (const float*)d_in[11];
    const float* vb2  = (const float*)d_in[12];
    const float* Wdot = (const float*)d_in[13];
    const float* Wout = (const float*)d_in[14];
    const float* Wf1  = (const float*)d_in[15];
    const float* Wf2  = (const float*)d_in[16];
    const int*   eidx = (const int*)d_in[17];
    float* out = (float*)d_out;

    k_pro1<<<PRO1_TOTAL, 256>>>(eidx, kW2, vW2, xf, Wq, Wdot, kb2, vb2,
                                sh, emb, elen, kW1, kb1, vW1, vb1);
    k_pro2<<<1257, 512>>>(xf);
    k_scatter<<<(EE + 255) / 256, 256>>>(eidx);
    k_edges<<<NN, 256>>>();
    k_final<<<(NN + 255) / 256, 256>>>(xf, Wout, Wf1, Wf2, out);
}